// round 1
// baseline (speedup 1.0000x reference)
#include <cuda_runtime.h>
#include <cuda_bf16.h>
#include <math.h>

// Problem constants (fixed by the reference setup_inputs)
#define NN 100000
#define HH 20000
#define EE 1600000
#define DD 64
#define FF 256
#define LL 3

// ---------------- scratch (static device globals; no runtime alloc) --------
__device__ __align__(16) float g_h  [NN * DD];   // current node features
__device__ __align__(16) float g_b1 [NN * DD];   // gemm-out Y / final LN out
__device__ __align__(16) float g_b2 [NN * DD];   // agg_n / FFN2 out
__device__ __align__(16) float g_t  [NN * FF];   // FFN hidden
__device__ __align__(16) float g_ha [HH * DD];   // hyperedge agg
__device__ __align__(16) float g_hb [HH * DD];   // hyperedge gemm out
__device__ float g_degn[NN];
__device__ float g_degh[HH];
__device__ float g_invn[NN];
__device__ float g_invh[HH];

// ---------------- utility kernels ------------------------------------------
__global__ void k_zero(float* __restrict__ p, int n) {
    int i = blockIdx.x * blockDim.x + threadIdx.x;
    int stride = gridDim.x * blockDim.x;
    for (; i < n; i += stride) p[i] = 0.0f;
}

__global__ void k_deg(const int* __restrict__ src, const int* __restrict__ dst,
                      float* __restrict__ degn, float* __restrict__ degh) {
    int e = blockIdx.x * blockDim.x + threadIdx.x;
    if (e < EE) {
        atomicAdd(&degn[src[e]], 1.0f);
        atomicAdd(&degh[dst[e]], 1.0f);
    }
}

__global__ void k_inv(const float* __restrict__ degn, const float* __restrict__ degh,
                      float* __restrict__ invn, float* __restrict__ invh) {
    int i = blockIdx.x * blockDim.x + threadIdx.x;
    if (i < NN) invn[i] = rsqrtf(fmaxf(degn[i], 1.0f));
    if (i < HH) invh[i] = rsqrtf(fmaxf(degh[i], 1.0f));
}

// ---------------- 64x64 GEMM with fused pre/post ops ------------------------
// MODE 0: x = A[r][k] * rs[r]                      (node->hyper conv input)
// MODE 1: x = (A[r][k]*rs[r] + bvec[k]) * rs[r]    (hyper agg finalize + rescale)
// MODE 2: x = A[r][k], post: += bpost[j]           (final projection)
template <int MODE>
__global__ void k_gemm64(const float* __restrict__ A, const float* __restrict__ W,
                         const float* __restrict__ rs, const float* __restrict__ bvec,
                         const float* __restrict__ bpost, float* __restrict__ C, int M) {
    __shared__ __align__(16) float As[64][68];
    __shared__ __align__(16) float Ws[64][68];
    const int tid = threadIdx.x;           // 128 threads
    const int row0 = blockIdx.x * 64;

    #pragma unroll 8
    for (int i = tid; i < 64 * 64; i += 128) {
        int k = i >> 6, j = i & 63;
        Ws[k][j] = W[i];
    }
    #pragma unroll 8
    for (int i = tid; i < 64 * 64; i += 128) {
        int r = i >> 6, k = i & 63;
        int gr = row0 + r;
        float v = 0.0f;
        if (gr < M) {
            v = A[gr * 64 + k];
            if (MODE == 0) v *= rs[gr];
            else if (MODE == 1) { float s = rs[gr]; v = (v * s + bvec[k]) * s; }
        }
        As[k][r] = v;
    }
    __syncthreads();

    const int cg = tid & 7, rg = tid >> 3;     // 8 col-groups x 16 row-groups
    const int c0 = cg * 8, r0 = rg * 4;
    float acc[4][8];
    #pragma unroll
    for (int i = 0; i < 4; i++)
        #pragma unroll
        for (int j = 0; j < 8; j++) acc[i][j] = 0.0f;

    #pragma unroll
    for (int k = 0; k < 64; k++) {
        float4 a4 = *(const float4*)&As[k][r0];
        float4 w0 = *(const float4*)&Ws[k][c0];
        float4 w1 = *(const float4*)&Ws[k][c0 + 4];
        float a[4] = {a4.x, a4.y, a4.z, a4.w};
        float w[8] = {w0.x, w0.y, w0.z, w0.w, w1.x, w1.y, w1.z, w1.w};
        #pragma unroll
        for (int i = 0; i < 4; i++)
            #pragma unroll
            for (int j = 0; j < 8; j++)
                acc[i][j] = fmaf(a[i], w[j], acc[i][j]);
    }

    #pragma unroll
    for (int i = 0; i < 4; i++) {
        int gr = row0 + r0 + i;
        if (gr < M) {
            #pragma unroll
            for (int j = 0; j < 8; j++) {
                float v = acc[i][j];
                if (MODE == 2) v += bpost[c0 + j];
                C[gr * 64 + c0 + j] = v;
            }
        }
    }
}

// ---------------- FFN1: T = relu(A[M,64] @ W1[64,256] + b1) -----------------
__global__ void k_ffn1(const float* __restrict__ A, const float* __restrict__ W1,
                       const float* __restrict__ b1, float* __restrict__ T, int M) {
    extern __shared__ __align__(16) float smem[];
    float* As = smem;                 // [64][68]
    float* Ws = smem + 64 * 68;       // [64][264]
    const int tid = threadIdx.x;      // 256 threads
    const int row0 = blockIdx.x * 64;

    #pragma unroll 8
    for (int i = tid; i < 64 * 256; i += 256) {
        int k = i >> 8, j = i & 255;
        Ws[k * 264 + j] = W1[i];
    }
    #pragma unroll 4
    for (int i = tid; i < 64 * 64; i += 256) {
        int r = i >> 6, k = i & 63;
        int gr = row0 + r;
        As[k * 68 + r] = (gr < M) ? A[gr * 64 + k] : 0.0f;
    }
    __syncthreads();

    const int rg = tid >> 5, cg = tid & 31;  // 8 row-groups x 32 col-groups
    const int r0 = rg * 8, c0 = cg * 8;
    float acc[8][8];
    #pragma unroll
    for (int i = 0; i < 8; i++)
        #pragma unroll
        for (int j = 0; j < 8; j++) acc[i][j] = 0.0f;

    #pragma unroll
    for (int k = 0; k < 64; k++) {
        float4 a0 = *(const float4*)&As[k * 68 + r0];
        float4 a1 = *(const float4*)&As[k * 68 + r0 + 4];
        float4 w0 = *(const float4*)&Ws[k * 264 + c0];
        float4 w1 = *(const float4*)&Ws[k * 264 + c0 + 4];
        float a[8] = {a0.x, a0.y, a0.z, a0.w, a1.x, a1.y, a1.z, a1.w};
        float w[8] = {w0.x, w0.y, w0.z, w0.w, w1.x, w1.y, w1.z, w1.w};
        #pragma unroll
        for (int i = 0; i < 8; i++)
            #pragma unroll
            for (int j = 0; j < 8; j++)
                acc[i][j] = fmaf(a[i], w[j], acc[i][j]);
    }

    float bj[8];
    #pragma unroll
    for (int j = 0; j < 8; j++) bj[j] = b1[c0 + j];
    #pragma unroll
    for (int i = 0; i < 8; i++) {
        int gr = row0 + r0 + i;
        if (gr < M) {
            #pragma unroll
            for (int j = 0; j < 8; j++) {
                float v = acc[i][j] + bj[j];
                T[gr * 256 + c0 + j] = fmaxf(v, 0.0f);
            }
        }
    }
}

// ---------------- FFN2: U = T[M,256] @ W2[256,64] + b2 ----------------------
__global__ void k_ffn2(const float* __restrict__ T, const float* __restrict__ W2,
                       const float* __restrict__ b2, float* __restrict__ U, int M) {
    extern __shared__ __align__(16) float smem[];
    float* Ws = smem;                  // [256][68]
    float* As = smem + 256 * 68;       // [64][132] per K-chunk
    const int tid = threadIdx.x;       // 256 threads
    const int row0 = blockIdx.x * 128;

    #pragma unroll 8
    for (int i = tid; i < 256 * 64; i += 256) {
        int k = i >> 6, j = i & 63;
        Ws[k * 68 + j] = W2[i];
    }

    const int rg = tid >> 4, cg = tid & 15;  // 16 row-groups x 16 col-groups
    const int r0 = rg * 8, c0 = cg * 4;
    float acc[8][4];
    #pragma unroll
    for (int i = 0; i < 8; i++)
        #pragma unroll
        for (int j = 0; j < 4; j++) acc[i][j] = 0.0f;

    for (int kc = 0; kc < 4; kc++) {
        __syncthreads();
        #pragma unroll 4
        for (int i = tid; i < 64 * 128; i += 256) {
            int r = i >> 6, k = i & 63;
            int gr = row0 + r;
            As[k * 132 + r] = (gr < M) ? T[gr * 256 + kc * 64 + k] : 0.0f;
        }
        __syncthreads();
        #pragma unroll
        for (int k = 0; k < 64; k++) {
            float4 a0 = *(const float4*)&As[k * 132 + r0];
            float4 a1 = *(const float4*)&As[k * 132 + r0 + 4];
            float4 w0 = *(const float4*)&Ws[(kc * 64 + k) * 68 + c0];
            float a[8] = {a0.x, a0.y, a0.z, a0.w, a1.x, a1.y, a1.z, a1.w};
            float w[4] = {w0.x, w0.y, w0.z, w0.w};
            #pragma unroll
            for (int i = 0; i < 8; i++)
                #pragma unroll
                for (int j = 0; j < 4; j++)
                    acc[i][j] = fmaf(a[i], w[j], acc[i][j]);
        }
    }

    float bj[4];
    #pragma unroll
    for (int j = 0; j < 4; j++) bj[j] = b2[c0 + j];
    #pragma unroll
    for (int i = 0; i < 8; i++) {
        int gr = row0 + r0 + i;
        if (gr < M) {
            #pragma unroll
            for (int j = 0; j < 4; j++)
                U[gr * 64 + c0 + j] = acc[i][j] + bj[j];
        }
    }
}

// ---------------- scatter: agg[to[e]] += Y[from[e]]  (float4 atomics) -------
__global__ void k_scatter(const float* __restrict__ Y, const int* __restrict__ from,
                          const int* __restrict__ to, float* __restrict__ agg) {
    int gid = blockIdx.x * blockDim.x + threadIdx.x;  // EE*16 threads total
    int e = gid >> 4;
    int c = gid & 15;
    int s = __ldg(&from[e]);
    int d = __ldg(&to[e]);
    float4 v = ((const float4*)Y)[s * 16 + c];
    atomicAdd(((float4*)agg) + d * 16 + c, v);
}

// ---------------- LayerNorm (one warp per row of 64) ------------------------
// MODE 0: x = base
// MODE 1: x = base + add*rs[row] + bvec[j]   (conv residual + bias)
// MODE 2: x = base + add                     (FFN residual)
template <int MODE>
__global__ void k_ln(const float* __restrict__ base, const float* __restrict__ add,
                     const float* __restrict__ rs, const float* __restrict__ bvec,
                     const float* __restrict__ g, const float* __restrict__ b,
                     float* __restrict__ out, int M) {
    const int warp = threadIdx.x >> 5;
    const int lane = threadIdx.x & 31;
    const int row = blockIdx.x * (blockDim.x >> 5) + warp;
    if (row >= M) return;
    const int i0 = row * 64 + lane;
    const int i1 = i0 + 32;

    float x0 = base[i0], x1 = base[i1];
    if (MODE == 1) {
        float s = rs[row];
        x0 = fmaf(add[i0], s, x0) + bvec[lane];
        x1 = fmaf(add[i1], s, x1) + bvec[lane + 32];
    } else if (MODE == 2) {
        x0 += add[i0];
        x1 += add[i1];
    }
    float sum = x0 + x1;
    #pragma unroll
    for (int o = 16; o; o >>= 1) sum += __shfl_xor_sync(0xffffffffu, sum, o);
    float mu = sum * (1.0f / 64.0f);
    float d0 = x0 - mu, d1 = x1 - mu;
    float vs = d0 * d0 + d1 * d1;
    #pragma unroll
    for (int o = 16; o; o >>= 1) vs += __shfl_xor_sync(0xffffffffu, vs, o);
    float inv = rsqrtf(vs * (1.0f / 64.0f) + 1e-5f);
    out[i0] = fmaf(d0 * inv, g[lane], b[lane]);
    out[i1] = fmaf(d1 * inv, g[lane + 32], b[lane + 32]);
}

// ---------------- orchestration ---------------------------------------------
extern "C" void kernel_launch(void* const* d_in, const int* in_sizes, int n_in,
                              void* d_out, int out_size) {
    const float* x    = (const float*)d_in[0];
    const int*   esrc = (const int*)d_in[1];
    const int*   edst = (const int*)d_in[2];
    // n_hyper scalar may or may not be materialized as an input
    const int wi = (n_in >= 20) ? 4 : 3;
    const float* Wn2h = (const float*)d_in[wi + 0];
    const float* bn2h = (const float*)d_in[wi + 1];
    const float* Wh2n = (const float*)d_in[wi + 2];
    const float* bh2n = (const float*)d_in[wi + 3];
    const float* W1   = (const float*)d_in[wi + 4];
    const float* b1   = (const float*)d_in[wi + 5];
    const float* W2   = (const float*)d_in[wi + 6];
    const float* b2   = (const float*)d_in[wi + 7];
    const float* g1   = (const float*)d_in[wi + 8];
    const float* be1  = (const float*)d_in[wi + 9];
    const float* g2   = (const float*)d_in[wi + 10];
    const float* be2  = (const float*)d_in[wi + 11];
    const float* gF   = (const float*)d_in[wi + 12];
    const float* bF   = (const float*)d_in[wi + 13];
    const float* Wo   = (const float*)d_in[wi + 14];
    const float* bo   = (const float*)d_in[wi + 15];

    float *p_h, *p_b1, *p_b2, *p_t, *p_ha, *p_hb, *p_degn, *p_degh, *p_invn, *p_invh;
    cudaGetSymbolAddress((void**)&p_h,    g_h);
    cudaGetSymbolAddress((void**)&p_b1,   g_b1);
    cudaGetSymbolAddress((void**)&p_b2,   g_b2);
    cudaGetSymbolAddress((void**)&p_t,    g_t);
    cudaGetSymbolAddress((void**)&p_ha,   g_ha);
    cudaGetSymbolAddress((void**)&p_hb,   g_hb);
    cudaGetSymbolAddress((void**)&p_degn, g_degn);
    cudaGetSymbolAddress((void**)&p_degh, g_degh);
    cudaGetSymbolAddress((void**)&p_invn, g_invn);
    cudaGetSymbolAddress((void**)&p_invh, g_invh);

    const int smem1 = (64 * 68 + 64 * 264) * (int)sizeof(float);   // ~85 KB
    const int smem2 = (256 * 68 + 64 * 132) * (int)sizeof(float);  // ~103 KB
    cudaFuncSetAttribute(k_ffn1, cudaFuncAttributeMaxDynamicSharedMemorySize, smem1);
    cudaFuncSetAttribute(k_ffn2, cudaFuncAttributeMaxDynamicSharedMemorySize, smem2);

    // h = node_features
    cudaMemcpyAsync(p_h, x, (size_t)NN * DD * sizeof(float), cudaMemcpyDeviceToDevice);

    // degrees -> inverse sqrt norms
    k_zero<<<512, 256>>>(p_degn, NN);
    k_zero<<<128, 256>>>(p_degh, HH);
    k_deg<<<(EE + 255) / 256, 256>>>(esrc, edst, p_degn, p_degh);
    k_inv<<<(NN + 255) / 256, 256>>>(p_degn, p_degh, p_invn, p_invh);

    const int gN64  = (NN + 63) / 64;    // 1563
    const int gH64  = (HH + 63) / 64;    // 313
    const int gN128 = (NN + 127) / 128;  // 782
    const int gLN   = (NN + 7) / 8;      // 12500
    const int gSC   = (EE * 16) / 256;   // 100000

    for (int l = 0; l < LL; l++) {
        const float* Wa = Wn2h + (size_t)l * DD * DD;
        const float* ba = bn2h + (size_t)l * DD;
        const float* Wb = Wh2n + (size_t)l * DD * DD;
        const float* bb = bh2n + (size_t)l * DD;
        const float* w1 = W1 + (size_t)l * DD * FF;
        const float* c1 = b1 + (size_t)l * FF;
        const float* w2 = W2 + (size_t)l * FF * DD;
        const float* c2 = b2 + (size_t)l * DD;
        const float* gg1 = g1 + (size_t)l * DD;
        const float* ee1 = be1 + (size_t)l * DD;
        const float* gg2 = g2 + (size_t)l * DD;
        const float* ee2 = be2 + (size_t)l * DD;

        // node -> hyperedge conv
        k_gemm64<0><<<gN64, 128>>>(p_h, Wa, p_invn, nullptr, nullptr, p_b1, NN);
        k_zero<<<1280, 256>>>(p_ha, HH * DD);
        k_scatter<<<gSC, 256>>>(p_b1, esrc, edst, p_ha);
        // hyperedge -> node conv (bias+norm fused into gemm pre-op)
        k_gemm64<1><<<gH64, 128>>>(p_ha, Wb, p_invh, ba, nullptr, p_hb, HH);
        k_zero<<<4096, 256>>>(p_b2, NN * DD);
        k_scatter<<<gSC, 256>>>(p_hb, edst, esrc, p_b2);
        // residual + LN1 (conv bias fused)
        k_ln<1><<<gLN, 256>>>(p_h, p_b2, p_invn, bb, gg1, ee1, p_h, NN);
        // FFN
        k_ffn1<<<gN64, 256, smem1>>>(p_h, w1, c1, p_t, NN);
        k_ffn2<<<gN128, 256, smem2>>>(p_t, w2, c2, p_b2, NN);
        // residual + LN2
        k_ln<2><<<gLN, 256>>>(p_h, p_b2, nullptr, nullptr, gg2, ee2, p_h, NN);
    }

    // final LN + output projection
    k_ln<0><<<gLN, 256>>>(p_h, nullptr, nullptr, nullptr, gF, bF, p_b1, NN);
    k_gemm64<2><<<gN64, 128>>>(p_b1, Wo, nullptr, nullptr, bo, (float*)d_out, NN);
}

// round 2
// speedup vs baseline: 1.1200x; 1.1200x over previous
#include <cuda_runtime.h>
#include <cuda_bf16.h>
#include <math.h>

// Problem constants (fixed by the reference setup_inputs)
#define NN 100000
#define HH 20000
#define EE 1600000
#define DD 64
#define FF 256
#define LL 3

// ---------------- packed f32x2 helpers (FFMA2) ------------------------------
typedef unsigned long long ull;

__device__ __forceinline__ ull pack2(float lo, float hi) {
    ull r;
    asm("mov.b64 %0, {%1, %2};" : "=l"(r) : "f"(lo), "f"(hi));
    return r;
}
__device__ __forceinline__ void unpack2(ull v, float& lo, float& hi) {
    asm("mov.b64 {%0, %1}, %2;" : "=f"(lo), "=f"(hi) : "l"(v));
}
__device__ __forceinline__ void ffma2(ull& d, ull a, ull b) {
    asm("fma.rn.f32x2 %0, %1, %2, %0;" : "+l"(d) : "l"(a), "l"(b));
}

// ---------------- scratch (static device globals; no runtime alloc) --------
__device__ __align__(16) float g_h  [NN * DD];   // current node features
__device__ __align__(16) float g_b1 [NN * DD];   // gemm-out Y / final LN out
__device__ __align__(16) float g_b2 [NN * DD];   // agg_n / FFN2 out
__device__ __align__(16) float g_t  [NN * FF];   // FFN hidden
__device__ __align__(16) float g_ha [HH * DD];   // hyperedge agg
__device__ __align__(16) float g_hb [HH * DD];   // hyperedge gemm out
__device__ float g_degn[NN];
__device__ float g_degh[HH];
__device__ float g_invn[NN];
__device__ float g_invh[HH];

// ---------------- utility kernels ------------------------------------------
__global__ void k_zero(float* __restrict__ p, int n) {
    int i = blockIdx.x * blockDim.x + threadIdx.x;
    int stride = gridDim.x * blockDim.x;
    for (; i < n; i += stride) p[i] = 0.0f;
}

__global__ void k_deg(const int* __restrict__ src, const int* __restrict__ dst,
                      float* __restrict__ degn, float* __restrict__ degh) {
    int e = blockIdx.x * blockDim.x + threadIdx.x;
    if (e < EE) {
        atomicAdd(&degn[src[e]], 1.0f);
        atomicAdd(&degh[dst[e]], 1.0f);
    }
}

__global__ void k_inv(const float* __restrict__ degn, const float* __restrict__ degh,
                      float* __restrict__ invn, float* __restrict__ invh) {
    int i = blockIdx.x * blockDim.x + threadIdx.x;
    if (i < NN) invn[i] = rsqrtf(fmaxf(degn[i], 1.0f));
    if (i < HH) invh[i] = rsqrtf(fmaxf(degh[i], 1.0f));
}

// ---------------- 64x64 GEMM with fused pre/post ops ------------------------
// MODE 0: x = A[r][k] * rs[r]                      (node->hyper conv input)
// MODE 1: x = (A[r][k]*rs[r] + bvec[k]) * rs[r]    (hyper agg finalize + rescale)
// MODE 2: x = A[r][k], post: += bpost[j]           (final projection)
template <int MODE>
__global__ void k_gemm64(const float* __restrict__ A, const float* __restrict__ W,
                         const float* __restrict__ rs, const float* __restrict__ bvec,
                         const float* __restrict__ bpost, float* __restrict__ C, int M) {
    __shared__ __align__(16) float As[64][68];
    __shared__ __align__(16) float Ws[64][68];
    const int tid = threadIdx.x;           // 128 threads
    const int row0 = blockIdx.x * 64;

    #pragma unroll 8
    for (int i = tid; i < 64 * 64; i += 128) {
        int k = i >> 6, j = i & 63;
        Ws[k][j] = W[i];
    }
    #pragma unroll 8
    for (int i = tid; i < 64 * 64; i += 128) {
        int r = i >> 6, k = i & 63;
        int gr = row0 + r;
        float v = 0.0f;
        if (gr < M) {
            v = A[gr * 64 + k];
            if (MODE == 0) v *= rs[gr];
            else if (MODE == 1) { float s = rs[gr]; v = (v * s + bvec[k]) * s; }
        }
        As[k][r] = v;
    }
    __syncthreads();

    const int cg = tid & 7, rg = tid >> 3;     // 8 col-groups x 16 row-groups
    const int c0 = cg * 8, r0 = rg * 4;
    // cols paired: accp[i][jp] holds cols (c0+2jp, c0+2jp+1) of row r0+i
    ull accp[4][4];
    #pragma unroll
    for (int i = 0; i < 4; i++)
        #pragma unroll
        for (int j = 0; j < 4; j++) accp[i][j] = 0ull;

    #pragma unroll
    for (int k = 0; k < 64; k++) {
        float4 a4 = *(const float4*)&As[k][r0];
        const ulonglong2* wp = (const ulonglong2*)&Ws[k][c0];
        ulonglong2 w01 = wp[0], w23 = wp[1];
        ull wpr[4] = {w01.x, w01.y, w23.x, w23.y};
        float a[4] = {a4.x, a4.y, a4.z, a4.w};
        ull ad[4];
        #pragma unroll
        for (int i = 0; i < 4; i++) ad[i] = pack2(a[i], a[i]);
        #pragma unroll
        for (int i = 0; i < 4; i++)
            #pragma unroll
            for (int jp = 0; jp < 4; jp++)
                ffma2(accp[i][jp], ad[i], wpr[jp]);
    }

    #pragma unroll
    for (int i = 0; i < 4; i++) {
        int gr = row0 + r0 + i;
        if (gr < M) {
            #pragma unroll
            for (int jp = 0; jp < 4; jp++) {
                float lo, hi;
                unpack2(accp[i][jp], lo, hi);
                if (MODE == 2) { lo += bpost[c0 + 2 * jp]; hi += bpost[c0 + 2 * jp + 1]; }
                C[gr * 64 + c0 + 2 * jp]     = lo;
                C[gr * 64 + c0 + 2 * jp + 1] = hi;
            }
        }
    }
}

// ---------------- FFN1: T = relu(A[M,64] @ W1[64,256] + b1) -----------------
__global__ void k_ffn1(const float* __restrict__ A, const float* __restrict__ W1,
                       const float* __restrict__ b1, float* __restrict__ T, int M) {
    extern __shared__ __align__(16) float smem[];
    float* As = smem;                 // [64][68]
    float* Ws = smem + 64 * 68;       // [64][264]
    const int tid = threadIdx.x;      // 256 threads
    const int row0 = blockIdx.x * 64;

    #pragma unroll 8
    for (int i = tid; i < 64 * 256; i += 256) {
        int k = i >> 8, j = i & 255;
        Ws[k * 264 + j] = W1[i];
    }
    #pragma unroll 4
    for (int i = tid; i < 64 * 64; i += 256) {
        int r = i >> 6, k = i & 63;
        int gr = row0 + r;
        As[k * 68 + r] = (gr < M) ? A[gr * 64 + k] : 0.0f;
    }
    __syncthreads();

    const int rg = tid >> 5, cg = tid & 31;  // 8 row-groups x 32 col-groups
    const int r0 = rg * 8, c0 = cg * 8;
    // cols paired: accp[i][jp] = cols (c0+2jp, c0+2jp+1) of row r0+i
    ull accp[8][4];
    #pragma unroll
    for (int i = 0; i < 8; i++)
        #pragma unroll
        for (int j = 0; j < 4; j++) accp[i][j] = 0ull;

    #pragma unroll
    for (int k = 0; k < 64; k++) {
        float4 a0 = *(const float4*)&As[k * 68 + r0];
        float4 a1 = *(const float4*)&As[k * 68 + r0 + 4];
        const ulonglong2* wp = (const ulonglong2*)&Ws[k * 264 + c0];
        ulonglong2 w01 = wp[0], w23 = wp[1];
        ull wpr[4] = {w01.x, w01.y, w23.x, w23.y};
        float a[8] = {a0.x, a0.y, a0.z, a0.w, a1.x, a1.y, a1.z, a1.w};
        ull ad[8];
        #pragma unroll
        for (int i = 0; i < 8; i++) ad[i] = pack2(a[i], a[i]);
        #pragma unroll
        for (int i = 0; i < 8; i++)
            #pragma unroll
            for (int jp = 0; jp < 4; jp++)
                ffma2(accp[i][jp], ad[i], wpr[jp]);
    }

    float bj[8];
    #pragma unroll
    for (int j = 0; j < 8; j++) bj[j] = b1[c0 + j];
    #pragma unroll
    for (int i = 0; i < 8; i++) {
        int gr = row0 + r0 + i;
        if (gr < M) {
            #pragma unroll
            for (int jp = 0; jp < 4; jp++) {
                float lo, hi;
                unpack2(accp[i][jp], lo, hi);
                T[gr * 256 + c0 + 2 * jp]     = fmaxf(lo + bj[2 * jp], 0.0f);
                T[gr * 256 + c0 + 2 * jp + 1] = fmaxf(hi + bj[2 * jp + 1], 0.0f);
            }
        }
    }
}

// ---------------- FFN2: U = T[M,256] @ W2[256,64] + b2 ----------------------
__global__ void k_ffn2(const float* __restrict__ T, const float* __restrict__ W2,
                       const float* __restrict__ b2, float* __restrict__ U, int M) {
    extern __shared__ __align__(16) float smem[];
    float* Ws = smem;                  // [256][68]
    float* As = smem + 256 * 68;       // [64][132] per K-chunk
    const int tid = threadIdx.x;       // 256 threads
    const int row0 = blockIdx.x * 128;

    #pragma unroll 8
    for (int i = tid; i < 256 * 64; i += 256) {
        int k = i >> 6, j = i & 63;
        Ws[k * 68 + j] = W2[i];
    }

    const int rg = tid >> 4, cg = tid & 15;  // 16 row-groups x 16 col-groups
    const int r0 = rg * 8, c0 = cg * 4;
    // rows paired: accp[ip][j] = rows (r0+2ip, r0+2ip+1) of col c0+j
    ull accp[4][4];
    #pragma unroll
    for (int i = 0; i < 4; i++)
        #pragma unroll
        for (int j = 0; j < 4; j++) accp[i][j] = 0ull;

    for (int kc = 0; kc < 4; kc++) {
        __syncthreads();
        #pragma unroll 4
        for (int i = tid; i < 64 * 128; i += 256) {
            int r = i >> 6, k = i & 63;
            int gr = row0 + r;
            As[k * 132 + r] = (gr < M) ? T[gr * 256 + kc * 64 + k] : 0.0f;
        }
        __syncthreads();
        #pragma unroll
        for (int k = 0; k < 64; k++) {
            const ulonglong2* ap = (const ulonglong2*)&As[k * 132 + r0];
            ulonglong2 a01 = ap[0], a23 = ap[1];
            ull apr[4] = {a01.x, a01.y, a23.x, a23.y};
            float4 w4 = *(const float4*)&Ws[(kc * 64 + k) * 68 + c0];
            float w[4] = {w4.x, w4.y, w4.z, w4.w};
            ull wd[4];
            #pragma unroll
            for (int j = 0; j < 4; j++) wd[j] = pack2(w[j], w[j]);
            #pragma unroll
            for (int ip = 0; ip < 4; ip++)
                #pragma unroll
                for (int j = 0; j < 4; j++)
                    ffma2(accp[ip][j], apr[ip], wd[j]);
        }
    }

    float bj[4];
    #pragma unroll
    for (int j = 0; j < 4; j++) bj[j] = b2[c0 + j];
    #pragma unroll
    for (int ip = 0; ip < 4; ip++) {
        int gr0 = row0 + r0 + 2 * ip;
        #pragma unroll
        for (int j = 0; j < 4; j++) {
            float lo, hi;
            unpack2(accp[ip][j], lo, hi);
            if (gr0 < M)     U[gr0 * 64 + c0 + j]       = lo + bj[j];
            if (gr0 + 1 < M) U[(gr0 + 1) * 64 + c0 + j] = hi + bj[j];
        }
    }
}

// ---------------- scatter: agg[to[e]] += Y[from[e]]  (float4 atomics) -------
__global__ void k_scatter(const float* __restrict__ Y, const int* __restrict__ from,
                          const int* __restrict__ to, float* __restrict__ agg) {
    int gid = blockIdx.x * blockDim.x + threadIdx.x;  // EE*16 threads total
    int e = gid >> 4;
    int c = gid & 15;
    int s = __ldg(&from[e]);
    int d = __ldg(&to[e]);
    float4 v = ((const float4*)Y)[s * 16 + c];
    atomicAdd(((float4*)agg) + d * 16 + c, v);
}

// ---------------- LayerNorm (one warp per row of 64) ------------------------
// MODE 0: x = base
// MODE 1: x = base + add*rs[row] + bvec[j]   (conv residual + bias)
// MODE 2: x = base + add                     (FFN residual)
template <int MODE>
__global__ void k_ln(const float* __restrict__ base, const float* __restrict__ add,
                     const float* __restrict__ rs, const float* __restrict__ bvec,
                     const float* __restrict__ g, const float* __restrict__ b,
                     float* __restrict__ out, int M) {
    const int warp = threadIdx.x >> 5;
    const int lane = threadIdx.x & 31;
    const int row = blockIdx.x * (blockDim.x >> 5) + warp;
    if (row >= M) return;
    const int i0 = row * 64 + lane;
    const int i1 = i0 + 32;

    float x0 = base[i0], x1 = base[i1];
    if (MODE == 1) {
        float s = rs[row];
        x0 = fmaf(add[i0], s, x0) + bvec[lane];
        x1 = fmaf(add[i1], s, x1) + bvec[lane + 32];
    } else if (MODE == 2) {
        x0 += add[i0];
        x1 += add[i1];
    }
    float sum = x0 + x1;
    #pragma unroll
    for (int o = 16; o; o >>= 1) sum += __shfl_xor_sync(0xffffffffu, sum, o);
    float mu = sum * (1.0f / 64.0f);
    float d0 = x0 - mu, d1 = x1 - mu;
    float vs = d0 * d0 + d1 * d1;
    #pragma unroll
    for (int o = 16; o; o >>= 1) vs += __shfl_xor_sync(0xffffffffu, vs, o);
    float inv = rsqrtf(vs * (1.0f / 64.0f) + 1e-5f);
    out[i0] = fmaf(d0 * inv, g[lane], b[lane]);
    out[i1] = fmaf(d1 * inv, g[lane + 32], b[lane + 32]);
}

// ---------------- orchestration ---------------------------------------------
extern "C" void kernel_launch(void* const* d_in, const int* in_sizes, int n_in,
                              void* d_out, int out_size) {
    const float* x    = (const float*)d_in[0];
    const int*   esrc = (const int*)d_in[1];
    const int*   edst = (const int*)d_in[2];
    // n_hyper scalar may or may not be materialized as an input
    const int wi = (n_in >= 20) ? 4 : 3;
    const float* Wn2h = (const float*)d_in[wi + 0];
    const float* bn2h = (const float*)d_in[wi + 1];
    const float* Wh2n = (const float*)d_in[wi + 2];
    const float* bh2n = (const float*)d_in[wi + 3];
    const float* W1   = (const float*)d_in[wi + 4];
    const float* b1   = (const float*)d_in[wi + 5];
    const float* W2   = (const float*)d_in[wi + 6];
    const float* b2   = (const float*)d_in[wi + 7];
    const float* g1   = (const float*)d_in[wi + 8];
    const float* be1  = (const float*)d_in[wi + 9];
    const float* g2   = (const float*)d_in[wi + 10];
    const float* be2  = (const float*)d_in[wi + 11];
    const float* gF   = (const float*)d_in[wi + 12];
    const float* bF   = (const float*)d_in[wi + 13];
    const float* Wo   = (const float*)d_in[wi + 14];
    const float* bo   = (const float*)d_in[wi + 15];

    float *p_h, *p_b1, *p_b2, *p_t, *p_ha, *p_hb, *p_degn, *p_degh, *p_invn, *p_invh;
    cudaGetSymbolAddress((void**)&p_h,    g_h);
    cudaGetSymbolAddress((void**)&p_b1,   g_b1);
    cudaGetSymbolAddress((void**)&p_b2,   g_b2);
    cudaGetSymbolAddress((void**)&p_t,    g_t);
    cudaGetSymbolAddress((void**)&p_ha,   g_ha);
    cudaGetSymbolAddress((void**)&p_hb,   g_hb);
    cudaGetSymbolAddress((void**)&p_degn, g_degn);
    cudaGetSymbolAddress((void**)&p_degh, g_degh);
    cudaGetSymbolAddress((void**)&p_invn, g_invn);
    cudaGetSymbolAddress((void**)&p_invh, g_invh);

    const int smem1 = (64 * 68 + 64 * 264) * (int)sizeof(float);   // ~85 KB
    const int smem2 = (256 * 68 + 64 * 132) * (int)sizeof(float);  // ~103 KB
    cudaFuncSetAttribute(k_ffn1, cudaFuncAttributeMaxDynamicSharedMemorySize, smem1);
    cudaFuncSetAttribute(k_ffn2, cudaFuncAttributeMaxDynamicSharedMemorySize, smem2);

    // h = node_features
    cudaMemcpyAsync(p_h, x, (size_t)NN * DD * sizeof(float), cudaMemcpyDeviceToDevice);

    // degrees -> inverse sqrt norms
    k_zero<<<512, 256>>>(p_degn, NN);
    k_zero<<<128, 256>>>(p_degh, HH);
    k_deg<<<(EE + 255) / 256, 256>>>(esrc, edst, p_degn, p_degh);
    k_inv<<<(NN + 255) / 256, 256>>>(p_degn, p_degh, p_invn, p_invh);

    const int gN64  = (NN + 63) / 64;    // 1563
    const int gH64  = (HH + 63) / 64;    // 313
    const int gN128 = (NN + 127) / 128;  // 782
    const int gLN   = (NN + 7) / 8;      // 12500
    const int gSC   = (EE * 16) / 256;   // 100000

    for (int l = 0; l < LL; l++) {
        const float* Wa = Wn2h + (size_t)l * DD * DD;
        const float* ba = bn2h + (size_t)l * DD;
        const float* Wb = Wh2n + (size_t)l * DD * DD;
        const float* bb = bh2n + (size_t)l * DD;
        const float* w1 = W1 + (size_t)l * DD * FF;
        const float* c1 = b1 + (size_t)l * FF;
        const float* w2 = W2 + (size_t)l * FF * DD;
        const float* c2 = b2 + (size_t)l * DD;
        const float* gg1 = g1 + (size_t)l * DD;
        const float* ee1 = be1 + (size_t)l * DD;
        const float* gg2 = g2 + (size_t)l * DD;
        const float* ee2 = be2 + (size_t)l * DD;

        // node -> hyperedge conv
        k_gemm64<0><<<gN64, 128>>>(p_h, Wa, p_invn, nullptr, nullptr, p_b1, NN);
        k_zero<<<1280, 256>>>(p_ha, HH * DD);
        k_scatter<<<gSC, 256>>>(p_b1, esrc, edst, p_ha);
        // hyperedge -> node conv (bias+norm fused into gemm pre-op)
        k_gemm64<1><<<gH64, 128>>>(p_ha, Wb, p_invh, ba, nullptr, p_hb, HH);
        k_zero<<<4096, 256>>>(p_b2, NN * DD);
        k_scatter<<<gSC, 256>>>(p_hb, edst, esrc, p_b2);
        // residual + LN1 (conv bias fused)
        k_ln<1><<<gLN, 256>>>(p_h, p_b2, p_invn, bb, gg1, ee1, p_h, NN);
        // FFN
        k_ffn1<<<gN64, 256, smem1>>>(p_h, w1, c1, p_t, NN);
        k_ffn2<<<gN128, 256, smem2>>>(p_t, w2, c2, p_b2, NN);
        // residual + LN2
        k_ln<2><<<gLN, 256>>>(p_h, p_b2, nullptr, nullptr, gg2, ee2, p_h, NN);
    }

    // final LN + output projection
    k_ln<0><<<gLN, 256>>>(p_h, nullptr, nullptr, nullptr, gF, bF, p_b1, NN);
    k_gemm64<2><<<gN64, 128>>>(p_b1, Wo, nullptr, nullptr, bo, (float*)d_out, NN);
}

// round 3
// speedup vs baseline: 1.2143x; 1.0842x over previous
#include <cuda_runtime.h>
#include <cuda_bf16.h>
#include <math.h>

// Problem constants (fixed by the reference setup_inputs)
#define NN 100000
#define HH 20000
#define EE 1600000
#define DD 64
#define FF 256
#define LL 3

// ---------------- packed f32x2 helpers (FFMA2) ------------------------------
typedef unsigned long long ull;

__device__ __forceinline__ ull pack2(float lo, float hi) {
    ull r;
    asm("mov.b64 %0, {%1, %2};" : "=l"(r) : "f"(lo), "f"(hi));
    return r;
}
__device__ __forceinline__ void unpack2(ull v, float& lo, float& hi) {
    asm("mov.b64 {%0, %1}, %2;" : "=f"(lo), "=f"(hi) : "l"(v));
}
__device__ __forceinline__ void ffma2(ull& d, ull a, ull b) {
    asm("fma.rn.f32x2 %0, %1, %2, %0;" : "+l"(d) : "l"(a), "l"(b));
}

// ---------------- scratch (static device globals; no runtime alloc) --------
__device__ __align__(16) float g_h  [NN * DD];   // current node features
__device__ __align__(16) float g_b1 [NN * DD];   // gemm-out Y / final LN out
__device__ __align__(16) float g_b2 [NN * DD];   // agg_n / FFN2 out
__device__ __align__(16) float g_t  [NN * FF];   // FFN hidden
__device__ __align__(16) float g_ha [HH * DD];   // hyperedge agg
__device__ __align__(16) float g_hb [HH * DD];   // hyperedge gemm out
__device__ float g_invn[NN];
__device__ float g_invh[HH];
// CSR structures (built per launch)
__device__ int g_cntH [HH];     // hyperedge in-degree
__device__ int g_cntN [NN];     // node out-degree
__device__ int g_startH[HH];
__device__ int g_startN[NN];
__device__ int g_curH [HH];
__device__ int g_curN [NN];
__device__ int g_csrH [EE];     // grouped by dst hyperedge -> src node ids
__device__ int g_csrN [EE];     // grouped by src node -> dst hyperedge ids

// ---------------- utility kernels ------------------------------------------
__global__ void k_zeroi(int* __restrict__ p, int n) {
    int i = blockIdx.x * blockDim.x + threadIdx.x;
    int stride = gridDim.x * blockDim.x;
    for (; i < n; i += stride) p[i] = 0;
}

__global__ void k_hist(const int* __restrict__ src, const int* __restrict__ dst,
                       int* __restrict__ cntN, int* __restrict__ cntH) {
    int e = blockIdx.x * blockDim.x + threadIdx.x;
    if (e < EE) {
        atomicAdd(&cntN[src[e]], 1);
        atomicAdd(&cntH[dst[e]], 1);
    }
}

// single-block exclusive scan (shuffle-based, chunks of 1024)
__global__ void k_scan(const int* __restrict__ cnt, int* __restrict__ start, int n) {
    __shared__ int shw[33];
    __shared__ int sh_carry;
    const int tid = threadIdx.x;
    const int lane = tid & 31, warp = tid >> 5;
    if (tid == 0) sh_carry = 0;
    __syncthreads();
    for (int base = 0; base < n; base += 1024) {
        int i = base + tid;
        int v = (i < n) ? cnt[i] : 0;
        // warp inclusive scan
        int inc = v;
        #pragma unroll
        for (int o = 1; o < 32; o <<= 1) {
            int t = __shfl_up_sync(0xffffffffu, inc, o);
            if (lane >= o) inc += t;
        }
        if (lane == 31) shw[warp] = inc;
        __syncthreads();
        if (warp == 0) {
            int t = shw[lane];
            int winc = t;
            #pragma unroll
            for (int o = 1; o < 32; o <<= 1) {
                int u = __shfl_up_sync(0xffffffffu, winc, o);
                if (lane >= o) winc += u;
            }
            shw[lane] = winc - t;          // exclusive warp offsets
            if (lane == 31) shw[32] = winc; // chunk total
        }
        __syncthreads();
        int carry = sh_carry;
        if (i < n) start[i] = carry + shw[warp] + inc - v;
        __syncthreads();
        if (tid == 0) sh_carry = carry + shw[32];
        __syncthreads();
    }
}

__global__ void k_fill(const int* __restrict__ src, const int* __restrict__ dst,
                       const int* __restrict__ startH, const int* __restrict__ startN,
                       int* __restrict__ curH, int* __restrict__ curN,
                       int* __restrict__ csrH, int* __restrict__ csrN) {
    int e = blockIdx.x * blockDim.x + threadIdx.x;
    if (e < EE) {
        int s = src[e], d = dst[e];
        int p = atomicAdd(&curH[d], 1);
        csrH[startH[d] + p] = s;
        int q = atomicAdd(&curN[s], 1);
        csrN[startN[s] + q] = d;
    }
}

__global__ void k_inv(const int* __restrict__ cntN, const int* __restrict__ cntH,
                      float* __restrict__ invn, float* __restrict__ invh) {
    int i = blockIdx.x * blockDim.x + threadIdx.x;
    if (i < NN) invn[i] = rsqrtf(fmaxf((float)cntN[i], 1.0f));
    if (i < HH) invh[i] = rsqrtf(fmaxf((float)cntH[i], 1.0f));
}

// ---------------- gather aggregation: out[r] = sum_{j in seg(r)} Y[csr[j]] --
// one warp per destination row; 16 lanes x float4 cover 64 floats; two edges
// in flight per iteration (half = lane>>4), combined by shfl at the end.
__global__ void k_agg(const float* __restrict__ Y, const int* __restrict__ csr,
                      const int* __restrict__ start, const int* __restrict__ cnt,
                      float* __restrict__ out, int M) {
    const int warp = threadIdx.x >> 5;
    const int lane = threadIdx.x & 31;
    const int row = blockIdx.x * (blockDim.x >> 5) + warp;
    if (row >= M) return;
    const int half = lane >> 4;      // 0 or 1
    const int q = lane & 15;         // float4 slot within row
    const int s0 = start[row];
    const int c  = cnt[row];
    const float4* __restrict__ Y4 = (const float4*)Y;

    float4 acc = make_float4(0.f, 0.f, 0.f, 0.f);
    int j = half;
    for (; j + 2 < c; j += 4) {
        int sa = __ldg(&csr[s0 + j]);
        int sb = __ldg(&csr[s0 + j + 2]);
        float4 va = Y4[(size_t)sa * 16 + q];
        float4 vb = Y4[(size_t)sb * 16 + q];
        acc.x += va.x; acc.y += va.y; acc.z += va.z; acc.w += va.w;
        acc.x += vb.x; acc.y += vb.y; acc.z += vb.z; acc.w += vb.w;
    }
    if (j < c) {
        int sa = __ldg(&csr[s0 + j]);
        float4 va = Y4[(size_t)sa * 16 + q];
        acc.x += va.x; acc.y += va.y; acc.z += va.z; acc.w += va.w;
    }
    // combine the two halves
    acc.x += __shfl_xor_sync(0xffffffffu, acc.x, 16);
    acc.y += __shfl_xor_sync(0xffffffffu, acc.y, 16);
    acc.z += __shfl_xor_sync(0xffffffffu, acc.z, 16);
    acc.w += __shfl_xor_sync(0xffffffffu, acc.w, 16);
    if (half == 0) ((float4*)out)[(size_t)row * 16 + q] = acc;
}

// ---------------- 64x64 GEMM with fused pre/post ops ------------------------
// MODE 0: x = A[r][k] * rs[r]                      (node->hyper conv input)
// MODE 1: x = (A[r][k]*rs[r] + bvec[k]) * rs[r]    (hyper agg finalize + rescale)
// MODE 2: x = A[r][k], post: += bpost[j]           (final projection)
template <int MODE>
__global__ void k_gemm64(const float* __restrict__ A, const float* __restrict__ W,
                         const float* __restrict__ rs, const float* __restrict__ bvec,
                         const float* __restrict__ bpost, float* __restrict__ C, int M) {
    __shared__ __align__(16) float As[64][68];
    __shared__ __align__(16) float Ws[64][68];
    const int tid = threadIdx.x;           // 128 threads
    const int row0 = blockIdx.x * 64;

    #pragma unroll 8
    for (int i = tid; i < 64 * 64; i += 128) {
        int k = i >> 6, j = i & 63;
        Ws[k][j] = W[i];
    }
    #pragma unroll 8
    for (int i = tid; i < 64 * 64; i += 128) {
        int r = i >> 6, k = i & 63;
        int gr = row0 + r;
        float v = 0.0f;
        if (gr < M) {
            v = A[gr * 64 + k];
            if (MODE == 0) v *= rs[gr];
            else if (MODE == 1) { float s = rs[gr]; v = (v * s + bvec[k]) * s; }
        }
        As[k][r] = v;
    }
    __syncthreads();

    const int cg = tid & 7, rg = tid >> 3;     // 8 col-groups x 16 row-groups
    const int c0 = cg * 8, r0 = rg * 4;
    ull accp[4][4];
    #pragma unroll
    for (int i = 0; i < 4; i++)
        #pragma unroll
        for (int j = 0; j < 4; j++) accp[i][j] = 0ull;

    #pragma unroll
    for (int k = 0; k < 64; k++) {
        float4 a4 = *(const float4*)&As[k][r0];
        const ulonglong2* wp = (const ulonglong2*)&Ws[k][c0];
        ulonglong2 w01 = wp[0], w23 = wp[1];
        ull wpr[4] = {w01.x, w01.y, w23.x, w23.y};
        float a[4] = {a4.x, a4.y, a4.z, a4.w};
        ull ad[4];
        #pragma unroll
        for (int i = 0; i < 4; i++) ad[i] = pack2(a[i], a[i]);
        #pragma unroll
        for (int i = 0; i < 4; i++)
            #pragma unroll
            for (int jp = 0; jp < 4; jp++)
                ffma2(accp[i][jp], ad[i], wpr[jp]);
    }

    #pragma unroll
    for (int i = 0; i < 4; i++) {
        int gr = row0 + r0 + i;
        if (gr < M) {
            #pragma unroll
            for (int jp = 0; jp < 4; jp++) {
                float lo, hi;
                unpack2(accp[i][jp], lo, hi);
                if (MODE == 2) { lo += bpost[c0 + 2 * jp]; hi += bpost[c0 + 2 * jp + 1]; }
                C[gr * 64 + c0 + 2 * jp]     = lo;
                C[gr * 64 + c0 + 2 * jp + 1] = hi;
            }
        }
    }
}

// ---------------- FFN1: T = relu(A[M,64] @ W1[64,256] + b1) -----------------
__global__ void k_ffn1(const float* __restrict__ A, const float* __restrict__ W1,
                       const float* __restrict__ b1, float* __restrict__ T, int M) {
    extern __shared__ __align__(16) float smem[];
    float* As = smem;                 // [64][68]
    float* Ws = smem + 64 * 68;       // [64][264]
    const int tid = threadIdx.x;      // 256 threads
    const int row0 = blockIdx.x * 64;

    #pragma unroll 8
    for (int i = tid; i < 64 * 256; i += 256) {
        int k = i >> 8, j = i & 255;
        Ws[k * 264 + j] = W1[i];
    }
    #pragma unroll 4
    for (int i = tid; i < 64 * 64; i += 256) {
        int r = i >> 6, k = i & 63;
        int gr = row0 + r;
        As[k * 68 + r] = (gr < M) ? A[gr * 64 + k] : 0.0f;
    }
    __syncthreads();

    const int rg = tid >> 5, cg = tid & 31;  // 8 row-groups x 32 col-groups
    const int r0 = rg * 8, c0 = cg * 8;
    ull accp[8][4];
    #pragma unroll
    for (int i = 0; i < 8; i++)
        #pragma unroll
        for (int j = 0; j < 4; j++) accp[i][j] = 0ull;

    #pragma unroll
    for (int k = 0; k < 64; k++) {
        float4 a0 = *(const float4*)&As[k * 68 + r0];
        float4 a1 = *(const float4*)&As[k * 68 + r0 + 4];
        const ulonglong2* wp = (const ulonglong2*)&Ws[k * 264 + c0];
        ulonglong2 w01 = wp[0], w23 = wp[1];
        ull wpr[4] = {w01.x, w01.y, w23.x, w23.y};
        float a[8] = {a0.x, a0.y, a0.z, a0.w, a1.x, a1.y, a1.z, a1.w};
        ull ad[8];
        #pragma unroll
        for (int i = 0; i < 8; i++) ad[i] = pack2(a[i], a[i]);
        #pragma unroll
        for (int i = 0; i < 8; i++)
            #pragma unroll
            for (int jp = 0; jp < 4; jp++)
                ffma2(accp[i][jp], ad[i], wpr[jp]);
    }

    float bj[8];
    #pragma unroll
    for (int j = 0; j < 8; j++) bj[j] = b1[c0 + j];
    #pragma unroll
    for (int i = 0; i < 8; i++) {
        int gr = row0 + r0 + i;
        if (gr < M) {
            #pragma unroll
            for (int jp = 0; jp < 4; jp++) {
                float lo, hi;
                unpack2(accp[i][jp], lo, hi);
                T[gr * 256 + c0 + 2 * jp]     = fmaxf(lo + bj[2 * jp], 0.0f);
                T[gr * 256 + c0 + 2 * jp + 1] = fmaxf(hi + bj[2 * jp + 1], 0.0f);
            }
        }
    }
}

// ---------------- FFN2: U = T[M,256] @ W2[256,64] + b2 ----------------------
__global__ void k_ffn2(const float* __restrict__ T, const float* __restrict__ W2,
                       const float* __restrict__ b2, float* __restrict__ U, int M) {
    extern __shared__ __align__(16) float smem[];
    float* Ws = smem;                  // [256][68]
    float* As = smem + 256 * 68;       // [64][132] per K-chunk
    const int tid = threadIdx.x;       // 256 threads
    const int row0 = blockIdx.x * 128;

    #pragma unroll 8
    for (int i = tid; i < 256 * 64; i += 256) {
        int k = i >> 6, j = i & 63;
        Ws[k * 68 + j] = W2[i];
    }

    const int rg = tid >> 4, cg = tid & 15;  // 16 row-groups x 16 col-groups
    const int r0 = rg * 8, c0 = cg * 4;
    ull accp[4][4];
    #pragma unroll
    for (int i = 0; i < 4; i++)
        #pragma unroll
        for (int j = 0; j < 4; j++) accp[i][j] = 0ull;

    for (int kc = 0; kc < 4; kc++) {
        __syncthreads();
        #pragma unroll 4
        for (int i = tid; i < 64 * 128; i += 256) {
            int r = i >> 6, k = i & 63;
            int gr = row0 + r;
            As[k * 132 + r] = (gr < M) ? T[gr * 256 + kc * 64 + k] : 0.0f;
        }
        __syncthreads();
        #pragma unroll
        for (int k = 0; k < 64; k++) {
            const ulonglong2* ap = (const ulonglong2*)&As[k * 132 + r0];
            ulonglong2 a01 = ap[0], a23 = ap[1];
            ull apr[4] = {a01.x, a01.y, a23.x, a23.y};
            float4 w4 = *(const float4*)&Ws[(kc * 64 + k) * 68 + c0];
            float w[4] = {w4.x, w4.y, w4.z, w4.w};
            ull wd[4];
            #pragma unroll
            for (int j = 0; j < 4; j++) wd[j] = pack2(w[j], w[j]);
            #pragma unroll
            for (int ip = 0; ip < 4; ip++)
                #pragma unroll
                for (int j = 0; j < 4; j++)
                    ffma2(accp[ip][j], apr[ip], wd[j]);
        }
    }

    float bj[4];
    #pragma unroll
    for (int j = 0; j < 4; j++) bj[j] = b2[c0 + j];
    #pragma unroll
    for (int ip = 0; ip < 4; ip++) {
        int gr0 = row0 + r0 + 2 * ip;
        #pragma unroll
        for (int j = 0; j < 4; j++) {
            float lo, hi;
            unpack2(accp[ip][j], lo, hi);
            if (gr0 < M)     U[gr0 * 64 + c0 + j]       = lo + bj[j];
            if (gr0 + 1 < M) U[(gr0 + 1) * 64 + c0 + j] = hi + bj[j];
        }
    }
}

// ---------------- LayerNorm (one warp per row of 64) ------------------------
// MODE 0: x = base
// MODE 1: x = base + add*rs[row] + bvec[j]   (conv residual + bias)
// MODE 2: x = base + add                     (FFN residual)
template <int MODE>
__global__ void k_ln(const float* __restrict__ base, const float* __restrict__ add,
                     const float* __restrict__ rs, const float* __restrict__ bvec,
                     const float* __restrict__ g, const float* __restrict__ b,
                     float* __restrict__ out, int M) {
    const int warp = threadIdx.x >> 5;
    const int lane = threadIdx.x & 31;
    const int row = blockIdx.x * (blockDim.x >> 5) + warp;
    if (row >= M) return;
    const int i0 = row * 64 + lane;
    const int i1 = i0 + 32;

    float x0 = base[i0], x1 = base[i1];
    if (MODE == 1) {
        float s = rs[row];
        x0 = fmaf(add[i0], s, x0) + bvec[lane];
        x1 = fmaf(add[i1], s, x1) + bvec[lane + 32];
    } else if (MODE == 2) {
        x0 += add[i0];
        x1 += add[i1];
    }
    float sum = x0 + x1;
    #pragma unroll
    for (int o = 16; o; o >>= 1) sum += __shfl_xor_sync(0xffffffffu, sum, o);
    float mu = sum * (1.0f / 64.0f);
    float d0 = x0 - mu, d1 = x1 - mu;
    float vs = d0 * d0 + d1 * d1;
    #pragma unroll
    for (int o = 16; o; o >>= 1) vs += __shfl_xor_sync(0xffffffffu, vs, o);
    float inv = rsqrtf(vs * (1.0f / 64.0f) + 1e-5f);
    out[i0] = fmaf(d0 * inv, g[lane], b[lane]);
    out[i1] = fmaf(d1 * inv, g[lane + 32], b[lane + 32]);
}

// ---------------- orchestration ---------------------------------------------
extern "C" void kernel_launch(void* const* d_in, const int* in_sizes, int n_in,
                              void* d_out, int out_size) {
    const float* x    = (const float*)d_in[0];
    const int*   esrc = (const int*)d_in[1];
    const int*   edst = (const int*)d_in[2];
    // n_hyper scalar may or may not be materialized as an input
    const int wi = (n_in >= 20) ? 4 : 3;
    const float* Wn2h = (const float*)d_in[wi + 0];
    const float* bn2h = (const float*)d_in[wi + 1];
    const float* Wh2n = (const float*)d_in[wi + 2];
    const float* bh2n = (const float*)d_in[wi + 3];
    const float* W1   = (const float*)d_in[wi + 4];
    const float* b1   = (const float*)d_in[wi + 5];
    const float* W2   = (const float*)d_in[wi + 6];
    const float* b2   = (const float*)d_in[wi + 7];
    const float* g1   = (const float*)d_in[wi + 8];
    const float* be1  = (const float*)d_in[wi + 9];
    const float* g2   = (const float*)d_in[wi + 10];
    const float* be2  = (const float*)d_in[wi + 11];
    const float* gF   = (const float*)d_in[wi + 12];
    const float* bF   = (const float*)d_in[wi + 13];
    const float* Wo   = (const float*)d_in[wi + 14];
    const float* bo   = (const float*)d_in[wi + 15];

    float *p_h, *p_b1, *p_b2, *p_t, *p_ha, *p_hb, *p_invn, *p_invh;
    int *p_cntH, *p_cntN, *p_stH, *p_stN, *p_cuH, *p_cuN, *p_csrH, *p_csrN;
    cudaGetSymbolAddress((void**)&p_h,    g_h);
    cudaGetSymbolAddress((void**)&p_b1,   g_b1);
    cudaGetSymbolAddress((void**)&p_b2,   g_b2);
    cudaGetSymbolAddress((void**)&p_t,    g_t);
    cudaGetSymbolAddress((void**)&p_ha,   g_ha);
    cudaGetSymbolAddress((void**)&p_hb,   g_hb);
    cudaGetSymbolAddress((void**)&p_invn, g_invn);
    cudaGetSymbolAddress((void**)&p_invh, g_invh);
    cudaGetSymbolAddress((void**)&p_cntH, g_cntH);
    cudaGetSymbolAddress((void**)&p_cntN, g_cntN);
    cudaGetSymbolAddress((void**)&p_stH,  g_startH);
    cudaGetSymbolAddress((void**)&p_stN,  g_startN);
    cudaGetSymbolAddress((void**)&p_cuH,  g_curH);
    cudaGetSymbolAddress((void**)&p_cuN,  g_curN);
    cudaGetSymbolAddress((void**)&p_csrH, g_csrH);
    cudaGetSymbolAddress((void**)&p_csrN, g_csrN);

    const int smem1 = (64 * 68 + 64 * 264) * (int)sizeof(float);   // ~85 KB
    const int smem2 = (256 * 68 + 64 * 132) * (int)sizeof(float);  // ~103 KB
    cudaFuncSetAttribute(k_ffn1, cudaFuncAttributeMaxDynamicSharedMemorySize, smem1);
    cudaFuncSetAttribute(k_ffn2, cudaFuncAttributeMaxDynamicSharedMemorySize, smem2);

    // h = node_features
    cudaMemcpyAsync(p_h, x, (size_t)NN * DD * sizeof(float), cudaMemcpyDeviceToDevice);

    // ---- build CSR (both directions) + degree norms ----
    k_zeroi<<<256, 256>>>(p_cntN, NN);
    k_zeroi<<<64, 256>>>(p_cntH, HH);
    k_zeroi<<<256, 256>>>(p_cuN, NN);
    k_zeroi<<<64, 256>>>(p_cuH, HH);
    k_hist<<<(EE + 255) / 256, 256>>>(esrc, edst, p_cntN, p_cntH);
    k_scan<<<1, 1024>>>(p_cntH, p_stH, HH);
    k_scan<<<1, 1024>>>(p_cntN, p_stN, NN);
    k_fill<<<(EE + 255) / 256, 256>>>(esrc, edst, p_stH, p_stN, p_cuH, p_cuN, p_csrH, p_csrN);
    k_inv<<<(NN + 255) / 256, 256>>>(p_cntN, p_cntH, p_invn, p_invh);

    const int gN64  = (NN + 63) / 64;    // 1563
    const int gH64  = (HH + 63) / 64;    // 313
    const int gN128 = (NN + 127) / 128;  // 782
    const int gLN   = (NN + 7) / 8;      // 12500
    const int gAgH  = (HH + 7) / 8;      // 2500
    const int gAgN  = (NN + 7) / 8;      // 12500

    for (int l = 0; l < LL; l++) {
        const float* Wa = Wn2h + (size_t)l * DD * DD;
        const float* ba = bn2h + (size_t)l * DD;
        const float* Wb = Wh2n + (size_t)l * DD * DD;
        const float* bb = bh2n + (size_t)l * DD;
        const float* w1 = W1 + (size_t)l * DD * FF;
        const float* c1 = b1 + (size_t)l * FF;
        const float* w2 = W2 + (size_t)l * FF * DD;
        const float* c2 = b2 + (size_t)l * DD;
        const float* gg1 = g1 + (size_t)l * DD;
        const float* ee1 = be1 + (size_t)l * DD;
        const float* gg2 = g2 + (size_t)l * DD;
        const float* ee2 = be2 + (size_t)l * DD;

        // node -> hyperedge conv: gemm then gather-aggregate into hyperedges
        k_gemm64<0><<<gN64, 128>>>(p_h, Wa, p_invn, nullptr, nullptr, p_b1, NN);
        k_agg<<<gAgH, 256>>>(p_b1, p_csrH, p_stH, p_cntH, p_ha, HH);
        // hyperedge -> node conv (bias+norm fused into gemm pre-op)
        k_gemm64<1><<<gH64, 128>>>(p_ha, Wb, p_invh, ba, nullptr, p_hb, HH);
        k_agg<<<gAgN, 256>>>(p_hb, p_csrN, p_stN, p_cntN, p_b2, NN);
        // residual + LN1 (conv bias fused)
        k_ln<1><<<gLN, 256>>>(p_h, p_b2, p_invn, bb, gg1, ee1, p_h, NN);
        // FFN
        k_ffn1<<<gN64, 256, smem1>>>(p_h, w1, c1, p_t, NN);
        k_ffn2<<<gN128, 256, smem2>>>(p_t, w2, c2, p_b2, NN);
        // residual + LN2
        k_ln<2><<<gLN, 256>>>(p_h, p_b2, nullptr, nullptr, gg2, ee2, p_h, NN);
    }

    // final LN + output projection
    k_ln<0><<<gLN, 256>>>(p_h, nullptr, nullptr, nullptr, gF, bF, p_b1, NN);
    k_gemm64<2><<<gN64, 128>>>(p_b1, Wo, nullptr, nullptr, bo, (float*)d_out, NN);
}

// round 5
// speedup vs baseline: 1.5289x; 1.2590x over previous
#include <cuda_runtime.h>
#include <cuda_bf16.h>
#include <cstdint>
#include <math.h>

// Problem constants (fixed by the reference setup_inputs)
#define NN 100000
#define HH 20000
#define EE 1600000
#define DD 64
#define FF 256
#define LL 3

// ---------------- mma.sync helpers (baseline sm_80+ features) ---------------
__device__ __forceinline__ uint32_t smem_u32(const void* p) {
    uint32_t a;
    asm("{ .reg .u64 t; cvta.to.shared.u64 t, %1; cvt.u32.u64 %0, t; }" : "=r"(a) : "l"(p));
    return a;
}
__device__ __forceinline__ void ldsm_x4(uint32_t* r, uint32_t addr) {
    asm volatile("ldmatrix.sync.aligned.m8n8.x4.shared.b16 {%0,%1,%2,%3}, [%4];"
                 : "=r"(r[0]), "=r"(r[1]), "=r"(r[2]), "=r"(r[3]) : "r"(addr));
}
__device__ __forceinline__ void ldsm_x2(uint32_t* r, uint32_t addr) {
    asm volatile("ldmatrix.sync.aligned.m8n8.x2.shared.b16 {%0,%1}, [%2];"
                 : "=r"(r[0]), "=r"(r[1]) : "r"(addr));
}
__device__ __forceinline__ void mma16816(float* d, const uint32_t* a, const uint32_t* b) {
    asm volatile("mma.sync.aligned.m16n8k16.row.col.f32.bf16.bf16.f32 "
                 "{%0,%1,%2,%3}, {%4,%5,%6,%7}, {%8,%9}, {%0,%1,%2,%3};"
                 : "+f"(d[0]), "+f"(d[1]), "+f"(d[2]), "+f"(d[3])
                 : "r"(a[0]), "r"(a[1]), "r"(a[2]), "r"(a[3]), "r"(b[0]), "r"(b[1]));
}

// split fp32 pair into bf16 hi/lo packed words
__device__ __forceinline__ void split2(float a, float b, uint32_t& hi, uint32_t& lo) {
    __nv_bfloat16 ha = __float2bfloat16(a), hb = __float2bfloat16(b);
    float ra = a - __bfloat162float(ha);
    float rb = b - __bfloat162float(hb);
    __nv_bfloat16 la = __float2bfloat16(ra), lb = __float2bfloat16(rb);
    hi = (uint32_t)__bfloat16_as_ushort(ha) | ((uint32_t)__bfloat16_as_ushort(hb) << 16);
    lo = (uint32_t)__bfloat16_as_ushort(la) | ((uint32_t)__bfloat16_as_ushort(lb) << 16);
}

// ---------------- scratch (static device globals; no runtime alloc) --------
__device__ __align__(16) float g_h  [NN * DD];
__device__ __align__(16) float g_b1 [NN * DD];
__device__ __align__(16) float g_b2 [NN * DD];
__device__ __align__(16) float g_t  [NN * FF];
__device__ __align__(16) float g_ha [HH * DD];
__device__ __align__(16) float g_hb [HH * DD];
__device__ float g_invn[NN];
__device__ float g_invh[HH];
__device__ int g_cntH [HH];
__device__ int g_cntN [NN];
__device__ int g_startH[HH];
__device__ int g_startN[NN];
__device__ int g_curH [HH];
__device__ int g_curN [NN];
__device__ int g_csrH [EE];
__device__ int g_csrN [EE];

// ---------------- CSR build kernels ------------------------------------------
__global__ void k_zeroi(int* __restrict__ p, int n) {
    int i = blockIdx.x * blockDim.x + threadIdx.x;
    int stride = gridDim.x * blockDim.x;
    for (; i < n; i += stride) p[i] = 0;
}

__global__ void k_hist(const int* __restrict__ src, const int* __restrict__ dst,
                       int* __restrict__ cntN, int* __restrict__ cntH) {
    int e = blockIdx.x * blockDim.x + threadIdx.x;
    if (e < EE) {
        atomicAdd(&cntN[src[e]], 1);
        atomicAdd(&cntH[dst[e]], 1);
    }
}

__global__ void k_scan(const int* __restrict__ cnt, int* __restrict__ start, int n) {
    __shared__ int shw[33];
    __shared__ int sh_carry;
    const int tid = threadIdx.x;
    const int lane = tid & 31, warp = tid >> 5;
    if (tid == 0) sh_carry = 0;
    __syncthreads();
    for (int base = 0; base < n; base += 1024) {
        int i = base + tid;
        int v = (i < n) ? cnt[i] : 0;
        int inc = v;
        #pragma unroll
        for (int o = 1; o < 32; o <<= 1) {
            int t = __shfl_up_sync(0xffffffffu, inc, o);
            if (lane >= o) inc += t;
        }
        if (lane == 31) shw[warp] = inc;
        __syncthreads();
        if (warp == 0) {
            int t = shw[lane];
            int winc = t;
            #pragma unroll
            for (int o = 1; o < 32; o <<= 1) {
                int u = __shfl_up_sync(0xffffffffu, winc, o);
                if (lane >= o) winc += u;
            }
            shw[lane] = winc - t;
            if (lane == 31) shw[32] = winc;
        }
        __syncthreads();
        int carry = sh_carry;
        if (i < n) start[i] = carry + shw[warp] + inc - v;
        __syncthreads();
        if (tid == 0) sh_carry = carry + shw[32];
        __syncthreads();
    }
}

__global__ void k_fill(const int* __restrict__ src, const int* __restrict__ dst,
                       const int* __restrict__ startH, const int* __restrict__ startN,
                       int* __restrict__ curH, int* __restrict__ curN,
                       int* __restrict__ csrH, int* __restrict__ csrN) {
    int e = blockIdx.x * blockDim.x + threadIdx.x;
    if (e < EE) {
        int s = src[e], d = dst[e];
        int p = atomicAdd(&curH[d], 1);
        csrH[startH[d] + p] = s;
        int q = atomicAdd(&curN[s], 1);
        csrN[startN[s] + q] = d;
    }
}

__global__ void k_inv(const int* __restrict__ cntN, const int* __restrict__ cntH,
                      float* __restrict__ invn, float* __restrict__ invh) {
    int i = blockIdx.x * blockDim.x + threadIdx.x;
    if (i < NN) invn[i] = rsqrtf(fmaxf((float)cntN[i], 1.0f));
    if (i < HH) invh[i] = rsqrtf(fmaxf((float)cntH[i], 1.0f));
}

// ---------------- gather aggregation ----------------------------------------
__global__ void k_agg(const float* __restrict__ Y, const int* __restrict__ csr,
                      const int* __restrict__ start, const int* __restrict__ cnt,
                      float* __restrict__ out, int M) {
    const int warp = threadIdx.x >> 5;
    const int lane = threadIdx.x & 31;
    const int row = blockIdx.x * (blockDim.x >> 5) + warp;
    if (row >= M) return;
    const int half = lane >> 4;
    const int q = lane & 15;
    const int s0 = start[row];
    const int c  = cnt[row];
    const float4* __restrict__ Y4 = (const float4*)Y;

    float4 acc = make_float4(0.f, 0.f, 0.f, 0.f);
    int j = half;
    for (; j + 2 < c; j += 4) {
        int sa = __ldg(&csr[s0 + j]);
        int sb = __ldg(&csr[s0 + j + 2]);
        float4 va = Y4[(size_t)sa * 16 + q];
        float4 vb = Y4[(size_t)sb * 16 + q];
        acc.x += va.x; acc.y += va.y; acc.z += va.z; acc.w += va.w;
        acc.x += vb.x; acc.y += vb.y; acc.z += vb.z; acc.w += vb.w;
    }
    if (j < c) {
        int sa = __ldg(&csr[s0 + j]);
        float4 va = Y4[(size_t)sa * 16 + q];
        acc.x += va.x; acc.y += va.y; acc.z += va.z; acc.w += va.w;
    }
    acc.x += __shfl_xor_sync(0xffffffffu, acc.x, 16);
    acc.y += __shfl_xor_sync(0xffffffffu, acc.y, 16);
    acc.z += __shfl_xor_sync(0xffffffffu, acc.z, 16);
    acc.w += __shfl_xor_sync(0xffffffffu, acc.w, 16);
    if (half == 0) ((float4*)out)[(size_t)row * 16 + q] = acc;
}

// ---------------- HMMA GEMM: C[M,NT] = pre(A)[M,KT] @ W[KT,NT] --------------
// 3-term bf16 split (Ahi*Whi + Ahi*Wlo + Alo*Whi), fp32 register accumulate.
// PRE: 0 none | 1 v*rs[r] | 2 (v*rs[r]+bvec[k])*rs[r]
// POST: 0 none | 1 +bpost[j] | 2 relu(v+bpost[j])
// Block: 128 rows x NT cols, 256 threads = 8 warps (4m x 2n).
template<int KT, int NT, int PRE, int POST>
__global__ void __launch_bounds__(256, 1)
k_mma(const float* __restrict__ A, const float* __restrict__ Wg,
      const float* __restrict__ rs, const float* __restrict__ bvec,
      const float* __restrict__ bpost, float* __restrict__ C, int M) {
    constexpr int KP = KT + 8;           // padded row (bf16 elems): conflict-free ldmatrix
    constexpr int KH = KT / 2;
    constexpr int A_ELEMS = 128 * KP;
    constexpr int B_ELEMS = NT * KP;
    extern __shared__ __align__(16) __nv_bfloat16 sm[];
    __nv_bfloat16* Ahi = sm;
    __nv_bfloat16* Alo = Ahi + A_ELEMS;
    __nv_bfloat16* Bhi = Alo + A_ELEMS;
    __nv_bfloat16* Blo = Bhi + B_ELEMS;

    const int tid = threadIdx.x;
    const int wid = tid >> 5, lane = tid & 31;
    const int row0 = blockIdx.x * 128;

    // ---- fill A tiles (hi/lo), pre-op fused; coalesced float2 loads ----
    for (int idx = tid; idx < 128 * KH; idx += 256) {
        int r = idx / KH, kp = idx - r * KH, k = kp * 2;
        int gr = row0 + r;
        float a0 = 0.f, a1 = 0.f;
        if (gr < M) {
            float2 t = ((const float2*)A)[(size_t)gr * KH + kp];
            a0 = t.x; a1 = t.y;
            if (PRE == 1) { float s = rs[gr]; a0 *= s; a1 *= s; }
            else if (PRE == 2) {
                float s = rs[gr];
                a0 = (a0 * s + bvec[k]) * s;
                a1 = (a1 * s + bvec[k + 1]) * s;
            }
        }
        uint32_t hi, lo; split2(a0, a1, hi, lo);
        *(uint32_t*)&Ahi[r * KP + k] = hi;
        *(uint32_t*)&Alo[r * KP + k] = lo;
    }
    // ---- fill B tiles: Bs[n][k] = W[k][n] (col-major for row.col mma) ----
    for (int idx = tid; idx < KH * NT; idx += 256) {
        int kp = idx / NT, n = idx - kp * NT, k = kp * 2;
        float w0 = __ldg(&Wg[(size_t)k * NT + n]);
        float w1 = __ldg(&Wg[(size_t)(k + 1) * NT + n]);
        uint32_t hi, lo; split2(w0, w1, hi, lo);
        *(uint32_t*)&Bhi[n * KP + k] = hi;
        *(uint32_t*)&Blo[n * KP + k] = lo;
    }
    __syncthreads();

    constexpr int NW = NT / 2;           // cols per warp
    constexpr int NF = NW / 8;           // n8 fragments per warp
    const int wm = wid & 3, wn = wid >> 2;
    const int mrow = wm * 32;
    const int ncol = wn * NW;

    float acc[2][NF][4];
    #pragma unroll
    for (int i = 0; i < 2; i++)
        #pragma unroll
        for (int nf = 0; nf < NF; nf++)
            #pragma unroll
            for (int j = 0; j < 4; j++) acc[i][nf][j] = 0.f;

    const uint32_t ahi_b = smem_u32(Ahi), alo_b = smem_u32(Alo);
    const uint32_t bhi_b = smem_u32(Bhi), blo_b = smem_u32(Blo);
    const int la  = lane & 15;
    const int lka = (lane >> 4) << 3;          // A: k half select
    const int lb  = lane & 7;
    const int lkb = ((lane >> 3) & 1) << 3;    // B: k half select (lanes 0-15)

    for (int kb = 0; kb < KT; kb += 16) {
        uint32_t ah[2][4], al[2][4];
        #pragma unroll
        for (int i = 0; i < 2; i++) {
            uint32_t aoff = (uint32_t)(((mrow + i * 16 + la) * KP + kb + lka) * 2);
            ldsm_x4(ah[i], ahi_b + aoff);
            ldsm_x4(al[i], alo_b + aoff);
        }
        #pragma unroll
        for (int nf = 0; nf < NF; nf++) {
            uint32_t boff = (uint32_t)(((ncol + nf * 8 + lb) * KP + kb + lkb) * 2);
            uint32_t bh[2], bl[2];
            ldsm_x2(bh, bhi_b + boff);
            ldsm_x2(bl, blo_b + boff);
            #pragma unroll
            for (int i = 0; i < 2; i++) {
                mma16816(acc[i][nf], ah[i], bh);
                mma16816(acc[i][nf], ah[i], bl);
                mma16816(acc[i][nf], al[i], bh);
            }
        }
    }

    // ---- epilogue: fragment -> global, POST fused ----
    const int qr = lane >> 2;
    const int qc = (lane & 3) * 2;
    #pragma unroll
    for (int i = 0; i < 2; i++) {
        #pragma unroll
        for (int half = 0; half < 2; half++) {
            int gr = row0 + mrow + i * 16 + half * 8 + qr;
            if (gr < M) {
                #pragma unroll
                for (int nf = 0; nf < NF; nf++) {
                    int c = ncol + nf * 8 + qc;
                    float v0 = acc[i][nf][half * 2 + 0];
                    float v1 = acc[i][nf][half * 2 + 1];
                    if (POST >= 1) { v0 += bpost[c]; v1 += bpost[c + 1]; }
                    if (POST == 2) { v0 = fmaxf(v0, 0.f); v1 = fmaxf(v1, 0.f); }
                    *(float2*)&C[(size_t)gr * NT + c] = make_float2(v0, v1);
                }
            }
        }
    }
}

// ---------------- LayerNorm (one warp per row of 64) ------------------------
template <int MODE>
__global__ void k_ln(const float* __restrict__ base, const float* __restrict__ add,
                     const float* __restrict__ rs, const float* __restrict__ bvec,
                     const float* __restrict__ g, const float* __restrict__ b,
                     float* __restrict__ out, int M) {
    const int warp = threadIdx.x >> 5;
    const int lane = threadIdx.x & 31;
    const int row = blockIdx.x * (blockDim.x >> 5) + warp;
    if (row >= M) return;
    const int i0 = row * 64 + lane;
    const int i1 = i0 + 32;

    float x0 = base[i0], x1 = base[i1];
    if (MODE == 1) {
        float s = rs[row];
        x0 = fmaf(add[i0], s, x0) + bvec[lane];
        x1 = fmaf(add[i1], s, x1) + bvec[lane + 32];
    } else if (MODE == 2) {
        x0 += add[i0];
        x1 += add[i1];
    }
    float sum = x0 + x1;
    #pragma unroll
    for (int o = 16; o; o >>= 1) sum += __shfl_xor_sync(0xffffffffu, sum, o);
    float mu = sum * (1.0f / 64.0f);
    float d0 = x0 - mu, d1 = x1 - mu;
    float vs = d0 * d0 + d1 * d1;
    #pragma unroll
    for (int o = 16; o; o >>= 1) vs += __shfl_xor_sync(0xffffffffu, vs, o);
    float inv = rsqrtf(vs * (1.0f / 64.0f) + 1e-5f);
    out[i0] = fmaf(d0 * inv, g[lane], b[lane]);
    out[i1] = fmaf(d1 * inv, g[lane + 32], b[lane + 32]);
}

// ---------------- orchestration ---------------------------------------------
extern "C" void kernel_launch(void* const* d_in, const int* in_sizes, int n_in,
                              void* d_out, int out_size) {
    const float* x    = (const float*)d_in[0];
    const int*   esrc = (const int*)d_in[1];
    const int*   edst = (const int*)d_in[2];
    const int wi = (n_in >= 20) ? 4 : 3;
    const float* Wn2h = (const float*)d_in[wi + 0];
    const float* bn2h = (const float*)d_in[wi + 1];
    const float* Wh2n = (const float*)d_in[wi + 2];
    const float* bh2n = (const float*)d_in[wi + 3];
    const float* W1   = (const float*)d_in[wi + 4];
    const float* b1   = (const float*)d_in[wi + 5];
    const float* W2   = (const float*)d_in[wi + 6];
    const float* b2   = (const float*)d_in[wi + 7];
    const float* g1   = (const float*)d_in[wi + 8];
    const float* be1  = (const float*)d_in[wi + 9];
    const float* g2   = (const float*)d_in[wi + 10];
    const float* be2  = (const float*)d_in[wi + 11];
    const float* gF   = (const float*)d_in[wi + 12];
    const float* bF   = (const float*)d_in[wi + 13];
    const float* Wo   = (const float*)d_in[wi + 14];
    const float* bo   = (const float*)d_in[wi + 15];

    float *p_h, *p_b1, *p_b2, *p_t, *p_ha, *p_hb, *p_invn, *p_invh;
    int *p_cntH, *p_cntN, *p_stH, *p_stN, *p_cuH, *p_cuN, *p_csrH, *p_csrN;
    cudaGetSymbolAddress((void**)&p_h,    g_h);
    cudaGetSymbolAddress((void**)&p_b1,   g_b1);
    cudaGetSymbolAddress((void**)&p_b2,   g_b2);
    cudaGetSymbolAddress((void**)&p_t,    g_t);
    cudaGetSymbolAddress((void**)&p_ha,   g_ha);
    cudaGetSymbolAddress((void**)&p_hb,   g_hb);
    cudaGetSymbolAddress((void**)&p_invn, g_invn);
    cudaGetSymbolAddress((void**)&p_invh, g_invh);
    cudaGetSymbolAddress((void**)&p_cntH, g_cntH);
    cudaGetSymbolAddress((void**)&p_cntN, g_cntN);
    cudaGetSymbolAddress((void**)&p_stH,  g_startH);
    cudaGetSymbolAddress((void**)&p_stN,  g_startN);
    cudaGetSymbolAddress((void**)&p_cuH,  g_curH);
    cudaGetSymbolAddress((void**)&p_cuN,  g_curN);
    cudaGetSymbolAddress((void**)&p_csrH, g_csrH);
    cudaGetSymbolAddress((void**)&p_csrN, g_csrN);

    // dynamic smem sizes (bf16 elems * 2 bytes)
    const int smem_conv = (2 * 128 * 72 + 2 * 64 * 72) * 2;     //  55296 B
    const int smem_ffn1 = (2 * 128 * 72 + 2 * 256 * 72) * 2;    // 110592 B
    const int smem_ffn2 = (2 * 128 * 264 + 2 * 64 * 264) * 2;   // 202752 B
    cudaFuncSetAttribute((const void*)k_mma<64, 64, 1, 0>,  cudaFuncAttributeMaxDynamicSharedMemorySize, smem_conv);
    cudaFuncSetAttribute((const void*)k_mma<64, 64, 2, 0>,  cudaFuncAttributeMaxDynamicSharedMemorySize, smem_conv);
    cudaFuncSetAttribute((const void*)k_mma<64, 64, 0, 1>,  cudaFuncAttributeMaxDynamicSharedMemorySize, smem_conv);
    cudaFuncSetAttribute((const void*)k_mma<64, 256, 0, 2>, cudaFuncAttributeMaxDynamicSharedMemorySize, smem_ffn1);
    cudaFuncSetAttribute((const void*)k_mma<256, 64, 0, 1>, cudaFuncAttributeMaxDynamicSharedMemorySize, smem_ffn2);

    // h = node_features
    cudaMemcpyAsync(p_h, x, (size_t)NN * DD * sizeof(float), cudaMemcpyDeviceToDevice);

    // ---- build CSR (both directions) + degree norms ----
    k_zeroi<<<256, 256>>>(p_cntN, NN);
    k_zeroi<<<64, 256>>>(p_cntH, HH);
    k_zeroi<<<256, 256>>>(p_cuN, NN);
    k_zeroi<<<64, 256>>>(p_cuH, HH);
    k_hist<<<(EE + 255) / 256, 256>>>(esrc, edst, p_cntN, p_cntH);
    k_scan<<<1, 1024>>>(p_cntH, p_stH, HH);
    k_scan<<<1, 1024>>>(p_cntN, p_stN, NN);
    k_fill<<<(EE + 255) / 256, 256>>>(esrc, edst, p_stH, p_stN, p_cuH, p_cuN, p_csrH, p_csrN);
    k_inv<<<(NN + 255) / 256, 256>>>(p_cntN, p_cntH, p_invn, p_invh);

    const int gN  = (NN + 127) / 128;  // 782
    const int gH  = (HH + 127) / 128;  // 157
    const int gLN = (NN + 7) / 8;      // 12500
    const int gAgH = (HH + 7) / 8;
    const int gAgN = (NN + 7) / 8;

    for (int l = 0; l < LL; l++) {
        const float* Wa = Wn2h + (size_t)l * DD * DD;
        const float* ba = bn2h + (size_t)l * DD;
        const float* Wb = Wh2n + (size_t)l * DD * DD;
        const float* bb = bh2n + (size_t)l * DD;
        const float* w1 = W1 + (size_t)l * DD * FF;
        const float* c1 = b1 + (size_t)l * FF;
        const float* w2 = W2 + (size_t)l * FF * DD;
        const float* c2 = b2 + (size_t)l * DD;
        const float* gg1 = g1 + (size_t)l * DD;
        const float* ee1 = be1 + (size_t)l * DD;
        const float* gg2 = g2 + (size_t)l * DD;
        const float* ee2 = be2 + (size_t)l * DD;

        // node -> hyperedge conv: scaled GEMM then gather into hyperedges
        k_mma<64, 64, 1, 0><<<gN, 256, smem_conv>>>(p_h, Wa, p_invn, nullptr, nullptr, p_b1, NN);
        k_agg<<<gAgH, 256>>>(p_b1, p_csrH, p_stH, p_cntH, p_ha, HH);
        // hyperedge -> node conv (bias + norms fused into pre-op)
        k_mma<64, 64, 2, 0><<<gH, 256, smem_conv>>>(p_ha, Wb, p_invh, ba, nullptr, p_hb, HH);
        k_agg<<<gAgN, 256>>>(p_hb, p_csrN, p_stN, p_cntN, p_b2, NN);
        // residual + LN1 (conv bias fused)
        k_ln<1><<<gLN, 256>>>(p_h, p_b2, p_invn, bb, gg1, ee1, p_h, NN);
        // FFN
        k_mma<64, 256, 0, 2><<<gN, 256, smem_ffn1>>>(p_h, w1, nullptr, nullptr, c1, p_t, NN);
        k_mma<256, 64, 0, 1><<<gN, 256, smem_ffn2>>>(p_t, w2, nullptr, nullptr, c2, p_b2, NN);
        // residual + LN2
        k_ln<2><<<gLN, 256>>>(p_h, p_b2, nullptr, nullptr, gg2, ee2, p_h, NN);
    }

    // final LN + output projection
    k_ln<0><<<gLN, 256>>>(p_h, nullptr, nullptr, nullptr, gF, bF, p_b1, NN);
    k_mma<64, 64, 0, 1><<<gN, 256, smem_conv>>>(p_b1, Wo, nullptr, nullptr, bo, (float*)d_out, NN);
}

// round 6
// speedup vs baseline: 1.9565x; 1.2797x over previous
#include <cuda_runtime.h>
#include <cuda_bf16.h>
#include <cstdint>
#include <math.h>

#define NN 100000
#define HH 20000
#define EE 1600000
#define DD 64
#define FF 256
#define LL 3

typedef unsigned short u16;

// ---------------- helpers ----------------------------------------------------
__device__ __forceinline__ uint32_t smem_u32(const void* p) {
    uint32_t a;
    asm("{ .reg .u64 t; cvta.to.shared.u64 t, %1; cvt.u32.u64 %0, t; }" : "=r"(a) : "l"(p));
    return a;
}
__device__ __forceinline__ void ldsm_x4(uint32_t* r, uint32_t addr) {
    asm volatile("ldmatrix.sync.aligned.m8n8.x4.shared.b16 {%0,%1,%2,%3}, [%4];"
                 : "=r"(r[0]), "=r"(r[1]), "=r"(r[2]), "=r"(r[3]) : "r"(addr));
}
__device__ __forceinline__ void ldsm_x2(uint32_t* r, uint32_t addr) {
    asm volatile("ldmatrix.sync.aligned.m8n8.x2.shared.b16 {%0,%1}, [%2];"
                 : "=r"(r[0]), "=r"(r[1]) : "r"(addr));
}
__device__ __forceinline__ void mma16816(float* d, const uint32_t* a, const uint32_t* b) {
    asm volatile("mma.sync.aligned.m16n8k16.row.col.f32.bf16.bf16.f32 "
                 "{%0,%1,%2,%3}, {%4,%5,%6,%7}, {%8,%9}, {%0,%1,%2,%3};"
                 : "+f"(d[0]), "+f"(d[1]), "+f"(d[2]), "+f"(d[3])
                 : "r"(a[0]), "r"(a[1]), "r"(a[2]), "r"(a[3]), "r"(b[0]), "r"(b[1]));
}
__device__ __forceinline__ void split2(float a, float b, uint32_t& hi, uint32_t& lo) {
    __nv_bfloat16 ha = __float2bfloat16(a), hb = __float2bfloat16(b);
    float ra = a - __bfloat162float(ha);
    float rb = b - __bfloat162float(hb);
    __nv_bfloat16 la = __float2bfloat16(ra), lb = __float2bfloat16(rb);
    hi = (uint32_t)__bfloat16_as_ushort(ha) | ((uint32_t)__bfloat16_as_ushort(hb) << 16);
    lo = (uint32_t)__bfloat16_as_ushort(la) | ((uint32_t)__bfloat16_as_ushort(lb) << 16);
}
// pack two floats to bf16x2 word: lo -> bits[15:0], hi -> bits[31:16]
__device__ __forceinline__ uint32_t pack_bf16(float lo, float hi) {
    uint32_t r;
    asm("cvt.rn.bf16x2.f32 %0, %1, %2;" : "=r"(r) : "f"(hi), "f"(lo));
    return r;
}

// ---------------- scratch ----------------------------------------------------
__device__ __align__(16) float g_h  [NN * DD];
__device__ __align__(16) float g_b1 [NN * DD];
__device__ __align__(16) float g_b2 [NN * DD];
__device__ __align__(16) float g_ha [HH * DD];   // z (agg into hyperedges)
__device__ __align__(16) float g_hb [HH * DD];   // w (g2 out)
__device__ __align__(16) u16 g_yhi [HH * DD];    // y split planes
__device__ __align__(16) u16 g_ylo [HH * DD];
__device__ __align__(16) u16 g_thi [NN * FF];    // FFN hidden (bf16, single plane)
// pre-split transposed weights [N][K] bf16 hi/lo
__device__ __align__(16) u16 g_wa_hi[LL * DD * DD];
__device__ __align__(16) u16 g_wa_lo[LL * DD * DD];
__device__ __align__(16) u16 g_wb_hi[LL * DD * DD];
__device__ __align__(16) u16 g_wb_lo[LL * DD * DD];
__device__ __align__(16) u16 g_w1_hi[LL * DD * FF];
__device__ __align__(16) u16 g_w1_lo[LL * DD * FF];
__device__ __align__(16) u16 g_w2_hi[LL * FF * DD];
__device__ __align__(16) u16 g_w2_lo[LL * FF * DD];
__device__ __align__(16) u16 g_wo_hi[DD * DD];
__device__ __align__(16) u16 g_wo_lo[DD * DD];
__device__ float g_invn[NN];
__device__ float g_invh[HH];
__device__ int g_cntH [HH];
__device__ int g_cntN [NN];
__device__ int g_startH[HH];
__device__ int g_startN[NN];
__device__ int g_curH [HH];
__device__ int g_curN [NN];
__device__ int g_csrH [EE];
__device__ int g_csrN [EE];

// ---------------- weight prep: fp32 [l][K][N] -> bf16 hi/lo [l][N][K] -------
__global__ void k_prep(const float* __restrict__ src, int K, int N, int total,
                       u16* __restrict__ hi, u16* __restrict__ lo) {
    int idx = blockIdx.x * blockDim.x + threadIdx.x;
    if (idx >= total) return;
    int KN = K * N;
    int l = idx / KN;
    int r = idx - l * KN;
    int k = r / N, n = r - k * N;
    float v = src[idx];
    __nv_bfloat16 h = __float2bfloat16(v);
    float res = v - __bfloat162float(h);
    __nv_bfloat16 lw = __float2bfloat16(res);
    size_t o = (size_t)l * KN + (size_t)n * K + k;
    hi[o] = __bfloat16_as_ushort(h);
    lo[o] = __bfloat16_as_ushort(lw);
}

// ---------------- CSR build --------------------------------------------------
__global__ void k_zeroi(int* __restrict__ p, int n) {
    int i = blockIdx.x * blockDim.x + threadIdx.x;
    int stride = gridDim.x * blockDim.x;
    for (; i < n; i += stride) p[i] = 0;
}

__global__ void k_hist(const int* __restrict__ src, const int* __restrict__ dst,
                       int* __restrict__ cntN, int* __restrict__ cntH) {
    int e = blockIdx.x * blockDim.x + threadIdx.x;
    if (e < EE) {
        atomicAdd(&cntN[src[e]], 1);
        atomicAdd(&cntH[dst[e]], 1);
    }
}

__global__ void k_scan(const int* __restrict__ cnt, int* __restrict__ start, int n) {
    __shared__ int shw[33];
    __shared__ int sh_carry;
    const int tid = threadIdx.x;
    const int lane = tid & 31, warp = tid >> 5;
    if (tid == 0) sh_carry = 0;
    __syncthreads();
    for (int base = 0; base < n; base += 1024) {
        int i = base + tid;
        int v = (i < n) ? cnt[i] : 0;
        int inc = v;
        #pragma unroll
        for (int o = 1; o < 32; o <<= 1) {
            int t = __shfl_up_sync(0xffffffffu, inc, o);
            if (lane >= o) inc += t;
        }
        if (lane == 31) shw[warp] = inc;
        __syncthreads();
        if (warp == 0) {
            int t = shw[lane];
            int winc = t;
            #pragma unroll
            for (int o = 1; o < 32; o <<= 1) {
                int u = __shfl_up_sync(0xffffffffu, winc, o);
                if (lane >= o) winc += u;
            }
            shw[lane] = winc - t;
            if (lane == 31) shw[32] = winc;
        }
        __syncthreads();
        int carry = sh_carry;
        if (i < n) start[i] = carry + shw[warp] + inc - v;
        __syncthreads();
        if (tid == 0) sh_carry = carry + shw[32];
        __syncthreads();
    }
}

__global__ void k_fill(const int* __restrict__ src, const int* __restrict__ dst,
                       const int* __restrict__ startH, const int* __restrict__ startN,
                       int* __restrict__ curH, int* __restrict__ curN,
                       int* __restrict__ csrH, int* __restrict__ csrN) {
    int e = blockIdx.x * blockDim.x + threadIdx.x;
    if (e < EE) {
        int s = src[e], d = dst[e];
        int p = atomicAdd(&curH[d], 1);
        csrH[startH[d] + p] = s;
        int q = atomicAdd(&curN[s], 1);
        csrN[startN[s] + q] = d;
    }
}

__global__ void k_inv(const int* __restrict__ cntN, const int* __restrict__ cntH,
                      float* __restrict__ invn, float* __restrict__ invh) {
    int i = blockIdx.x * blockDim.x + threadIdx.x;
    if (i < NN) invn[i] = rsqrtf(fmaxf((float)cntN[i], 1.0f));
    if (i < HH) invh[i] = rsqrtf(fmaxf((float)cntH[i], 1.0f));
}

// ---------------- gather aggregation (optional per-source scale) -------------
__global__ void k_agg(const float* __restrict__ Y, const int* __restrict__ csr,
                      const int* __restrict__ start, const int* __restrict__ cnt,
                      const float* __restrict__ scale, float* __restrict__ out, int M) {
    const int warp = threadIdx.x >> 5;
    const int lane = threadIdx.x & 31;
    const int row = blockIdx.x * (blockDim.x >> 5) + warp;
    if (row >= M) return;
    const int half = lane >> 4;
    const int q = lane & 15;
    const int s0 = start[row];
    const int c  = cnt[row];
    const float4* __restrict__ Y4 = (const float4*)Y;

    float4 acc = make_float4(0.f, 0.f, 0.f, 0.f);
    int j = half;
    for (; j + 2 < c; j += 4) {
        int sa = __ldg(&csr[s0 + j]);
        int sb = __ldg(&csr[s0 + j + 2]);
        float4 va = Y4[(size_t)sa * 16 + q];
        float4 vb = Y4[(size_t)sb * 16 + q];
        if (scale) {
            float fa = __ldg(&scale[sa]), fb = __ldg(&scale[sb]);
            va.x *= fa; va.y *= fa; va.z *= fa; va.w *= fa;
            vb.x *= fb; vb.y *= fb; vb.z *= fb; vb.w *= fb;
        }
        acc.x += va.x; acc.y += va.y; acc.z += va.z; acc.w += va.w;
        acc.x += vb.x; acc.y += vb.y; acc.z += vb.z; acc.w += vb.w;
    }
    if (j < c) {
        int sa = __ldg(&csr[s0 + j]);
        float4 va = Y4[(size_t)sa * 16 + q];
        if (scale) {
            float fa = __ldg(&scale[sa]);
            va.x *= fa; va.y *= fa; va.z *= fa; va.w *= fa;
        }
        acc.x += va.x; acc.y += va.y; acc.z += va.z; acc.w += va.w;
    }
    acc.x += __shfl_xor_sync(0xffffffffu, acc.x, 16);
    acc.y += __shfl_xor_sync(0xffffffffu, acc.y, 16);
    acc.z += __shfl_xor_sync(0xffffffffu, acc.z, 16);
    acc.w += __shfl_xor_sync(0xffffffffu, acc.w, 16);
    if (half == 0) ((float4*)out)[(size_t)row * 16 + q] = acc;
}

// ---------------- HMMA GEMM --------------------------------------------------
// ASPLIT: 0 = fp32 A (split on load, 3-term) | 1 = pre-split bf16 A (3-term)
//         2 = single-plane bf16 A (2-term)
// POST:   0 = fp32 out | 1 = fp32 out + bvec
//         3 = y=(v*rs[r]+bvec[c])*rs[r], split -> Chi/Clo
//         4 = relu(v+bvec[c]) -> Chi (single plane)
template<int KT, int NT, int ASPLIT, int POST>
__global__ void __launch_bounds__(256, 1)
k_mma(const float* __restrict__ A, const u16* __restrict__ Ahi_g,
      const u16* __restrict__ Alo_g,
      const u16* __restrict__ Whi_g, const u16* __restrict__ Wlo_g,
      const float* __restrict__ rs, const float* __restrict__ bvec,
      float* __restrict__ C, u16* __restrict__ Chi_g, u16* __restrict__ Clo_g,
      int M) {
    constexpr int KP = KT + 8;
    constexpr bool HAS_ALO = (ASPLIT != 2);
    constexpr int A_ELEMS = 128 * KP;
    constexpr int B_ELEMS = NT * KP;
    extern __shared__ __align__(16) u16 sm[];
    u16* Ahi = sm;
    u16* Alo = HAS_ALO ? (Ahi + A_ELEMS) : Ahi;
    u16* Bhi = (HAS_ALO ? Alo : Ahi) + A_ELEMS;
    u16* Blo = Bhi + B_ELEMS;

    const int tid = threadIdx.x;
    const int wid = tid >> 5, lane = tid & 31;
    const int row0 = blockIdx.x * 128;

    // ---- fill A ----
    if (ASPLIT == 0) {
        constexpr int KH = KT / 2;
        for (int idx = tid; idx < 128 * KH; idx += 256) {
            int r = idx / KH, kp = idx - r * KH, k = kp * 2;
            int gr = row0 + r;
            float a0 = 0.f, a1 = 0.f;
            if (gr < M) {
                float2 t = ((const float2*)A)[(size_t)gr * KH + kp];
                a0 = t.x; a1 = t.y;
            }
            uint32_t hi, lo; split2(a0, a1, hi, lo);
            *(uint32_t*)&Ahi[r * KP + k] = hi;
            *(uint32_t*)&Alo[r * KP + k] = lo;
        }
    } else {
        constexpr int K8 = KT / 8;
        const uint4 z4 = make_uint4(0, 0, 0, 0);
        for (int idx = tid; idx < 128 * K8; idx += 256) {
            int r = idx / K8, k8 = idx - r * K8;
            int gr = row0 + r;
            uint4 vh = z4;
            if (gr < M) vh = *(const uint4*)&Ahi_g[(size_t)gr * KT + k8 * 8];
            *(uint4*)&Ahi[r * KP + k8 * 8] = vh;
            if (ASPLIT == 1) {
                uint4 vl = z4;
                if (gr < M) vl = *(const uint4*)&Alo_g[(size_t)gr * KT + k8 * 8];
                *(uint4*)&Alo[r * KP + k8 * 8] = vl;
            }
        }
    }
    // ---- fill B (pre-split, pre-transposed [NT][KT]) ----
    {
        constexpr int K8 = KT / 8;
        for (int idx = tid; idx < NT * K8; idx += 256) {
            int n = idx / K8, k8 = idx - n * K8;
            *(uint4*)&Bhi[n * KP + k8 * 8] = *(const uint4*)&Whi_g[(size_t)n * KT + k8 * 8];
            *(uint4*)&Blo[n * KP + k8 * 8] = *(const uint4*)&Wlo_g[(size_t)n * KT + k8 * 8];
        }
    }
    __syncthreads();

    constexpr int NW = NT / 2;
    constexpr int NF = NW / 8;
    const int wm = wid & 3, wn = wid >> 2;
    const int mrow = wm * 32;
    const int ncol = wn * NW;

    float acc[2][NF][4];
    #pragma unroll
    for (int i = 0; i < 2; i++)
        #pragma unroll
        for (int nf = 0; nf < NF; nf++)
            #pragma unroll
            for (int j = 0; j < 4; j++) acc[i][nf][j] = 0.f;

    const uint32_t ahi_b = smem_u32(Ahi), alo_b = smem_u32(Alo);
    const uint32_t bhi_b = smem_u32(Bhi), blo_b = smem_u32(Blo);
    const int la  = lane & 15;
    const int lka = (lane >> 4) << 3;
    const int lb  = lane & 7;
    const int lkb = ((lane >> 3) & 1) << 3;

    for (int kb = 0; kb < KT; kb += 16) {
        uint32_t ah[2][4], al[2][4];
        #pragma unroll
        for (int i = 0; i < 2; i++) {
            uint32_t aoff = (uint32_t)(((mrow + i * 16 + la) * KP + kb + lka) * 2);
            ldsm_x4(ah[i], ahi_b + aoff);
            if (HAS_ALO) ldsm_x4(al[i], alo_b + aoff);
        }
        #pragma unroll
        for (int nf = 0; nf < NF; nf++) {
            uint32_t boff = (uint32_t)(((ncol + nf * 8 + lb) * KP + kb + lkb) * 2);
            uint32_t bh[2], bl[2];
            ldsm_x2(bh, bhi_b + boff);
            ldsm_x2(bl, blo_b + boff);
            #pragma unroll
            for (int i = 0; i < 2; i++) {
                mma16816(acc[i][nf], ah[i], bh);
                mma16816(acc[i][nf], ah[i], bl);
                if (HAS_ALO) mma16816(acc[i][nf], al[i], bh);
            }
        }
    }

    // ---- epilogue ----
    const int qr = lane >> 2;
    const int qc = (lane & 3) * 2;
    #pragma unroll
    for (int i = 0; i < 2; i++) {
        #pragma unroll
        for (int half = 0; half < 2; half++) {
            int gr = row0 + mrow + i * 16 + half * 8 + qr;
            if (gr < M) {
                float s = (POST == 3) ? rs[gr] : 0.f;
                #pragma unroll
                for (int nf = 0; nf < NF; nf++) {
                    int c = ncol + nf * 8 + qc;
                    float v0 = acc[i][nf][half * 2 + 0];
                    float v1 = acc[i][nf][half * 2 + 1];
                    if (POST == 1) {
                        v0 += bvec[c]; v1 += bvec[c + 1];
                        *(float2*)&C[(size_t)gr * NT + c] = make_float2(v0, v1);
                    } else if (POST == 3) {
                        float y0 = (v0 * s + bvec[c]) * s;
                        float y1 = (v1 * s + bvec[c + 1]) * s;
                        __nv_bfloat16 h0 = __float2bfloat16(y0);
                        __nv_bfloat16 h1 = __float2bfloat16(y1);
                        float l0 = y0 - __bfloat162float(h0);
                        float l1 = y1 - __bfloat162float(h1);
                        size_t w = ((size_t)gr * NT + c) >> 1;
                        ((uint32_t*)Chi_g)[w] = (uint32_t)__bfloat16_as_ushort(h0)
                                              | ((uint32_t)__bfloat16_as_ushort(h1) << 16);
                        ((uint32_t*)Clo_g)[w] = pack_bf16(l0, l1);
                    } else if (POST == 4) {
                        float t0 = fmaxf(v0 + bvec[c], 0.f);
                        float t1 = fmaxf(v1 + bvec[c + 1], 0.f);
                        ((uint32_t*)Chi_g)[((size_t)gr * NT + c) >> 1] = pack_bf16(t0, t1);
                    } else {
                        *(float2*)&C[(size_t)gr * NT + c] = make_float2(v0, v1);
                    }
                }
            }
        }
    }
}

// ---------------- LayerNorm --------------------------------------------------
template <int MODE>
__global__ void k_ln(const float* __restrict__ base, const float* __restrict__ add,
                     const float* __restrict__ rs, const float* __restrict__ bvec,
                     const float* __restrict__ g, const float* __restrict__ b,
                     float* __restrict__ out, int M) {
    const int warp = threadIdx.x >> 5;
    const int lane = threadIdx.x & 31;
    const int row = blockIdx.x * (blockDim.x >> 5) + warp;
    if (row >= M) return;
    const int i0 = row * 64 + lane;
    const int i1 = i0 + 32;

    float x0 = base[i0], x1 = base[i1];
    if (MODE == 1) {
        float s = rs[row];
        x0 = fmaf(add[i0], s, x0) + bvec[lane];
        x1 = fmaf(add[i1], s, x1) + bvec[lane + 32];
    } else if (MODE == 2) {
        x0 += add[i0];
        x1 += add[i1];
    }
    float sum = x0 + x1;
    #pragma unroll
    for (int o = 16; o; o >>= 1) sum += __shfl_xor_sync(0xffffffffu, sum, o);
    float mu = sum * (1.0f / 64.0f);
    float d0 = x0 - mu, d1 = x1 - mu;
    float vs = d0 * d0 + d1 * d1;
    #pragma unroll
    for (int o = 16; o; o >>= 1) vs += __shfl_xor_sync(0xffffffffu, vs, o);
    float inv = rsqrtf(vs * (1.0f / 64.0f) + 1e-5f);
    out[i0] = fmaf(d0 * inv, g[lane], b[lane]);
    out[i1] = fmaf(d1 * inv, g[lane + 32], b[lane + 32]);
}

// ---------------- orchestration ----------------------------------------------
extern "C" void kernel_launch(void* const* d_in, const int* in_sizes, int n_in,
                              void* d_out, int out_size) {
    const float* x    = (const float*)d_in[0];
    const int*   esrc = (const int*)d_in[1];
    const int*   edst = (const int*)d_in[2];
    const int wi = (n_in >= 20) ? 4 : 3;
    const float* Wn2h = (const float*)d_in[wi + 0];
    const float* bn2h = (const float*)d_in[wi + 1];
    const float* Wh2n = (const float*)d_in[wi + 2];
    const float* bh2n = (const float*)d_in[wi + 3];
    const float* W1   = (const float*)d_in[wi + 4];
    const float* b1   = (const float*)d_in[wi + 5];
    const float* W2   = (const float*)d_in[wi + 6];
    const float* b2   = (const float*)d_in[wi + 7];
    const float* g1   = (const float*)d_in[wi + 8];
    const float* be1  = (const float*)d_in[wi + 9];
    const float* g2   = (const float*)d_in[wi + 10];
    const float* be2  = (const float*)d_in[wi + 11];
    const float* gF   = (const float*)d_in[wi + 12];
    const float* bF   = (const float*)d_in[wi + 13];
    const float* Wo   = (const float*)d_in[wi + 14];
    const float* bo   = (const float*)d_in[wi + 15];

    float *p_h, *p_b1, *p_b2, *p_ha, *p_hb, *p_invn, *p_invh;
    u16 *p_yhi, *p_ylo, *p_thi;
    u16 *p_wa_hi, *p_wa_lo, *p_wb_hi, *p_wb_lo, *p_w1_hi, *p_w1_lo;
    u16 *p_w2_hi, *p_w2_lo, *p_wo_hi, *p_wo_lo;
    int *p_cntH, *p_cntN, *p_stH, *p_stN, *p_cuH, *p_cuN, *p_csrH, *p_csrN;
    cudaGetSymbolAddress((void**)&p_h,    g_h);
    cudaGetSymbolAddress((void**)&p_b1,   g_b1);
    cudaGetSymbolAddress((void**)&p_b2,   g_b2);
    cudaGetSymbolAddress((void**)&p_ha,   g_ha);
    cudaGetSymbolAddress((void**)&p_hb,   g_hb);
    cudaGetSymbolAddress((void**)&p_yhi,  g_yhi);
    cudaGetSymbolAddress((void**)&p_ylo,  g_ylo);
    cudaGetSymbolAddress((void**)&p_thi,  g_thi);
    cudaGetSymbolAddress((void**)&p_wa_hi, g_wa_hi);
    cudaGetSymbolAddress((void**)&p_wa_lo, g_wa_lo);
    cudaGetSymbolAddress((void**)&p_wb_hi, g_wb_hi);
    cudaGetSymbolAddress((void**)&p_wb_lo, g_wb_lo);
    cudaGetSymbolAddress((void**)&p_w1_hi, g_w1_hi);
    cudaGetSymbolAddress((void**)&p_w1_lo, g_w1_lo);
    cudaGetSymbolAddress((void**)&p_w2_hi, g_w2_hi);
    cudaGetSymbolAddress((void**)&p_w2_lo, g_w2_lo);
    cudaGetSymbolAddress((void**)&p_wo_hi, g_wo_hi);
    cudaGetSymbolAddress((void**)&p_wo_lo, g_wo_lo);
    cudaGetSymbolAddress((void**)&p_invn, g_invn);
    cudaGetSymbolAddress((void**)&p_invh, g_invh);
    cudaGetSymbolAddress((void**)&p_cntH, g_cntH);
    cudaGetSymbolAddress((void**)&p_cntN, g_cntN);
    cudaGetSymbolAddress((void**)&p_stH,  g_startH);
    cudaGetSymbolAddress((void**)&p_stN,  g_startN);
    cudaGetSymbolAddress((void**)&p_cuH,  g_curH);
    cudaGetSymbolAddress((void**)&p_cuN,  g_curN);
    cudaGetSymbolAddress((void**)&p_csrH, g_csrH);
    cudaGetSymbolAddress((void**)&p_csrN, g_csrN);

    // smem sizes (u16 elems * 2B)
    const int smem_conv = (2 * 128 * 72 + 2 * 64 * 72) * 2;     //  55296
    const int smem_ffn1 = (2 * 128 * 72 + 2 * 256 * 72) * 2;    // 110592
    const int smem_ffn2 = (1 * 128 * 264 + 2 * 64 * 264) * 2;   // 135168
    cudaFuncSetAttribute((const void*)k_mma<64, 64, 0, 3>,  cudaFuncAttributeMaxDynamicSharedMemorySize, smem_conv);
    cudaFuncSetAttribute((const void*)k_mma<64, 64, 1, 0>,  cudaFuncAttributeMaxDynamicSharedMemorySize, smem_conv);
    cudaFuncSetAttribute((const void*)k_mma<64, 64, 0, 1>,  cudaFuncAttributeMaxDynamicSharedMemorySize, smem_conv);
    cudaFuncSetAttribute((const void*)k_mma<64, 256, 0, 4>, cudaFuncAttributeMaxDynamicSharedMemorySize, smem_ffn1);
    cudaFuncSetAttribute((const void*)k_mma<256, 64, 2, 1>, cudaFuncAttributeMaxDynamicSharedMemorySize, smem_ffn2);

    cudaMemcpyAsync(p_h, x, (size_t)NN * DD * sizeof(float), cudaMemcpyDeviceToDevice);

    // ---- weight pre-split (transposed bf16 hi/lo) ----
    k_prep<<<(LL * DD * DD + 255) / 256, 256>>>(Wn2h, DD, DD, LL * DD * DD, p_wa_hi, p_wa_lo);
    k_prep<<<(LL * DD * DD + 255) / 256, 256>>>(Wh2n, DD, DD, LL * DD * DD, p_wb_hi, p_wb_lo);
    k_prep<<<(LL * DD * FF + 255) / 256, 256>>>(W1, DD, FF, LL * DD * FF, p_w1_hi, p_w1_lo);
    k_prep<<<(LL * FF * DD + 255) / 256, 256>>>(W2, FF, DD, LL * FF * DD, p_w2_hi, p_w2_lo);
    k_prep<<<(DD * DD + 255) / 256, 256>>>(Wo, DD, DD, DD * DD, p_wo_hi, p_wo_lo);

    // ---- build CSR + degree norms ----
    k_zeroi<<<256, 256>>>(p_cntN, NN);
    k_zeroi<<<64, 256>>>(p_cntH, HH);
    k_zeroi<<<256, 256>>>(p_cuN, NN);
    k_zeroi<<<64, 256>>>(p_cuH, HH);
    k_hist<<<(EE + 255) / 256, 256>>>(esrc, edst, p_cntN, p_cntH);
    k_scan<<<1, 1024>>>(p_cntH, p_stH, HH);
    k_scan<<<1, 1024>>>(p_cntN, p_stN, NN);
    k_fill<<<(EE + 255) / 256, 256>>>(esrc, edst, p_stH, p_stN, p_cuH, p_cuN, p_csrH, p_csrN);
    k_inv<<<(NN + 255) / 256, 256>>>(p_cntN, p_cntH, p_invn, p_invh);

    const int gN  = (NN + 127) / 128;  // 782
    const int gH  = (HH + 127) / 128;  // 157
    const int gLN = (NN + 7) / 8;
    const int gAgH = (HH + 7) / 8;
    const int gAgN = (NN + 7) / 8;

    for (int l = 0; l < LL; l++) {
        const float* ba = bn2h + (size_t)l * DD;
        const float* bb = bh2n + (size_t)l * DD;
        const float* c1 = b1 + (size_t)l * FF;
        const float* c2 = b2 + (size_t)l * DD;
        const float* gg1 = g1 + (size_t)l * DD;
        const float* ee1 = be1 + (size_t)l * DD;
        const float* gg2 = g2 + (size_t)l * DD;
        const float* ee2 = be2 + (size_t)l * DD;

        // z = agg_H(h * invn[src])   (linearity: aggregate before GEMM)
        k_agg<<<gAgH, 256>>>(p_h, p_csrH, p_stH, p_cntH, p_invn, p_ha, HH);
        // y = (z@Wa * invh + ba) * invh   -> split bf16 planes
        k_mma<64, 64, 0, 3><<<gH, 256, smem_conv>>>(
            p_ha, nullptr, nullptr, p_wa_hi + (size_t)l * DD * DD, p_wa_lo + (size_t)l * DD * DD,
            p_invh, ba, nullptr, p_yhi, p_ylo, HH);
        // w = y @ Wb
        k_mma<64, 64, 1, 0><<<gH, 256, smem_conv>>>(
            nullptr, p_yhi, p_ylo, p_wb_hi + (size_t)l * DD * DD, p_wb_lo + (size_t)l * DD * DD,
            nullptr, nullptr, p_hb, nullptr, nullptr, HH);
        // u = agg_N(w)
        k_agg<<<gAgN, 256>>>(p_hb, p_csrN, p_stN, p_cntN, nullptr, p_b2, NN);
        // h = LN(h + u*invn + bb)
        k_ln<1><<<gLN, 256>>>(p_h, p_b2, p_invn, bb, gg1, ee1, p_h, NN);
        // FFN1: T = relu(h@W1 + c1) -> bf16 single plane
        k_mma<64, 256, 0, 4><<<gN, 256, smem_ffn1>>>(
            p_h, nullptr, nullptr, p_w1_hi + (size_t)l * DD * FF, p_w1_lo + (size_t)l * DD * FF,
            nullptr, c1, nullptr, p_thi, nullptr, NN);
        // FFN2: U = T@W2 + c2 (2-term)
        k_mma<256, 64, 2, 1><<<gN, 256, smem_ffn2>>>(
            nullptr, p_thi, nullptr, p_w2_hi + (size_t)l * FF * DD, p_w2_lo + (size_t)l * FF * DD,
            nullptr, c2, p_b2, nullptr, nullptr, NN);
        // h = LN(h + U)
        k_ln<2><<<gLN, 256>>>(p_h, p_b2, nullptr, nullptr, gg2, ee2, p_h, NN);
    }

    // final LN + projection
    k_ln<0><<<gLN, 256>>>(p_h, nullptr, nullptr, nullptr, gF, bF, p_b1, NN);
    k_mma<64, 64, 0, 1><<<gN, 256, smem_conv>>>(
        p_b1, nullptr, nullptr, p_wo_hi, p_wo_lo, nullptr, bo, (float*)d_out, nullptr, nullptr, NN);
}